// round 14
// baseline (speedup 1.0000x reference)
#include <cuda_runtime.h>
#include <cuda_bf16.h>
#include <math.h>
#include <stdint.h>

#define Bn   4
#define Ss   512
#define Dd   512
#define Hh   8
#define DKk  64
#define Nl   6
#define Vv   32000
#define FFf  2048
#define TOK  (Bn*Ss)

// ---------------- fp32 scratch ----------------
__device__ __align__(16) float g_x[TOK*Dd];
__device__ __align__(16) float g_y[TOK*Dd];
__device__ __align__(16) float g_tmp[TOK*Dd];

// ---------------- packed bf16x2 hi/lo ----------------
#define DD2  (Dd*Dd/2)
__device__ __align__(16) uint32_t g_encW_h[24*DD2], g_encW_l[24*DD2];
__device__ __align__(16) uint32_t g_decSW_h[24*DD2], g_decSW_l[24*DD2];
__device__ __align__(16) uint32_t g_decCW_h[24*DD2], g_decCW_l[24*DD2];
#define W1SZ (Dd*FFf/2)
__device__ __align__(16) uint32_t g_encW1_h[Nl*W1SZ], g_encW1_l[Nl*W1SZ];
__device__ __align__(16) uint32_t g_encW2_h[Nl*W1SZ], g_encW2_l[Nl*W1SZ];
__device__ __align__(16) uint32_t g_decW1_h[Nl*W1SZ], g_decW1_l[Nl*W1SZ];
__device__ __align__(16) uint32_t g_decW2_h[Nl*W1SZ], g_decW2_l[Nl*W1SZ];
#define OWSZ (Dd*Vv/2)
__device__ __align__(16) uint32_t g_outW_h[OWSZ], g_outW_l[OWSZ];
#define KVC  (TOK*Dd/2)
__device__ __align__(16) uint32_t g_xT_h[KVC],  g_xT_l[KVC];        // activation packed (layout per use)
__device__ __align__(16) uint32_t g_qkvP_h[3*KVC], g_qkvP_l[3*KVC]; // q^T | k^T | vP
__device__ __align__(16) uint32_t g_oT_h[KVC],  g_oT_l[KVC];        // attn out^T packed
__device__ __align__(16) uint32_t g_xeT_h[KVC], g_xeT_l[KVC];       // encoder out^T packed
__device__ __align__(16) uint32_t g_xKV_h[12*KVC], g_xKV_l[12*KVC]; // cross K^T|V pairs, 6 layers
#define FTSZ ((FFf/2)*TOK)
__device__ __align__(16) uint32_t g_fT_h[FTSZ], g_fT_l[FTSZ];       // ffn hidden (frag layout)

// ---------------- helpers ----------------
__device__ __forceinline__ void cvt_pair(float x0, float x1, uint32_t& hi, uint32_t& lo)
{
    uint32_t h;
    asm("cvt.rn.bf16x2.f32 %0, %1, %2;" : "=r"(h) : "f"(x1), "f"(x0));
    __nv_bfloat162 hb = *reinterpret_cast<__nv_bfloat162*>(&h);
    float r0 = x0 - __bfloat162float(hb.x);
    float r1 = x1 - __bfloat162float(hb.y);
    uint32_t l;
    asm("cvt.rn.bf16x2.f32 %0, %1, %2;" : "=r"(l) : "f"(r1), "f"(r0));
    hi = h; lo = l;
}

__device__ __forceinline__ uint32_t mulbf2(uint32_t a, uint32_t b)
{
    uint32_t d; asm("mul.rn.bf16x2 %0,%1,%2;" : "=r"(d) : "r"(a), "r"(b)); return d;
}

__device__ __forceinline__ void mma16816(float* c, const uint32_t* a, const uint32_t* b)
{
    asm volatile(
        "mma.sync.aligned.m16n8k16.row.col.f32.bf16.bf16.f32 "
        "{%0,%1,%2,%3}, {%4,%5,%6,%7}, {%8,%9}, {%0,%1,%2,%3};\n"
        : "+f"(c[0]), "+f"(c[1]), "+f"(c[2]), "+f"(c[3])
        : "r"(a[0]), "r"(a[1]), "r"(a[2]), "r"(a[3]), "r"(b[0]), "r"(b[1]));
}

__device__ __forceinline__ void cp_async16(uint32_t s, const void* g)
{
    asm volatile("cp.async.cg.shared.global [%0], [%1], 16;" :: "r"(s), "l"(g));
}
#define CP_COMMIT() asm volatile("cp.async.commit_group;")

__device__ __forceinline__ void cp_wait_n(int n)
{
    switch (n) {
    case 0: asm volatile("cp.async.wait_group 0;"); break;
    case 1: asm volatile("cp.async.wait_group 1;"); break;
    case 2: asm volatile("cp.async.wait_group 2;"); break;
    default: asm volatile("cp.async.wait_group 3;"); break;
    }
}

// ---------------- conversion kernels ----------------
__global__ __launch_bounds__(256)
void convB(const float* __restrict__ W, uint32_t* __restrict__ H,
           uint32_t* __restrict__ L, int C)
{
    long long kp = blockIdx.y;
    int c = blockIdx.x * 256 + threadIdx.x;
    float a = W[(2*kp) * (long long)C + c];
    float b = W[(2*kp+1) * (long long)C + c];
    uint32_t h, l; cvt_pair(a, b, h, l);
    long long o = kp * C + c;
    H[o] = h; L[o] = l;
}

__global__ __launch_bounds__(256)
void convAT(const float* __restrict__ X, uint32_t* __restrict__ H,
            uint32_t* __restrict__ L, int Mdim, int Kdim)
{
    __shared__ float s[32][33];
    int m0 = blockIdx.x * 32, k0 = blockIdx.y * 32;
    int tx = threadIdx.x & 31, ty = threadIdx.x >> 5;
#pragma unroll
    for (int i = 0; i < 4; i++) {
        int m = ty + i * 8;
        s[m][tx] = X[(long long)(m0 + m) * Kdim + k0 + tx];
    }
    __syncthreads();
    int om = threadIdx.x & 31, okp = threadIdx.x >> 5;
#pragma unroll
    for (int i = 0; i < 2; i++) {
        int kp = okp + i * 8;
        uint32_t h, l;
        cvt_pair(s[om][2*kp], s[om][2*kp+1], h, l);
        long long o = (long long)(k0/2 + kp) * Mdim + m0 + om;
        H[o] = h; L[o] = l;
    }
}

// X[M][Ktot] fp32 -> A-frag layout [Ktot/16][M/16][32][4]
__global__ __launch_bounds__(256)
void convAF(const float* __restrict__ X, uint32_t* __restrict__ H,
            uint32_t* __restrict__ L, int Ktot, int Mtiles)
{
    __shared__ float s[128][20];
    int m0 = blockIdx.x * 128, kb = blockIdx.y;
    int t = threadIdx.x;
#pragma unroll
    for (int i = 0; i < 2; i++) {
        int li = t + i * 256;
        int r = li >> 2, c4 = li & 3;
        *reinterpret_cast<float4*>(&s[r][c4 * 4]) =
            *reinterpret_cast<const float4*>(&X[(long long)(m0 + r) * Ktot + kb * 16 + c4 * 4]);
    }
    __syncthreads();
    int w = t >> 5, lane = t & 31, group = (lane >> 2), tig = lane & 3;
    uint32_t hv[4], lv[4];
#pragma unroll
    for (int jhi = 0; jhi < 2; jhi++)
#pragma unroll
        for (int jlo = 0; jlo < 2; jlo++) {
            int kp_l = tig + 4 * jhi;
            int m_l = w * 16 + group + 8 * jlo;
            cvt_pair(s[m_l][2*kp_l], s[m_l][2*kp_l + 1], hv[jhi*2 + jlo], lv[jhi*2 + jlo]);
        }
    long long base = ((long long)(kb * Mtiles + blockIdx.x * 8 + w) * 32 + lane) * 4;
    *reinterpret_cast<uint4*>(&H[base]) = make_uint4(hv[0], hv[1], hv[2], hv[3]);
    *reinterpret_cast<uint4*>(&L[base]) = make_uint4(lv[0], lv[1], lv[2], lv[3]);
}

// W[K][N] fp32 -> B-frag layout [K/16][N/8][32][2]  (z = matrix index)
__global__ __launch_bounds__(256)
void convWF(const float* __restrict__ W, uint32_t* __restrict__ H,
            uint32_t* __restrict__ L, int K, int N)
{
    __shared__ float s[16][132];
    const float* Wz = W + (long long)blockIdx.z * K * N;
    long long zoff = (long long)blockIdx.z * (K / 16) * (N / 8) * 64;
    uint32_t* Hz = H + zoff;
    uint32_t* Lz = L + zoff;
    int n0 = blockIdx.x * 128, kb = blockIdx.y;
    int t = threadIdx.x;
#pragma unroll
    for (int i = 0; i < 2; i++) {
        int li = t + i * 256;
        int r = li >> 5, c4 = li & 31;
        *reinterpret_cast<float4*>(&s[r][c4 * 4]) =
            *reinterpret_cast<const float4*>(&Wz[(long long)(kb * 16 + r) * N + n0 + c4 * 4]);
    }
    __syncthreads();
    int Nt8 = N / 8;
#pragma unroll
    for (int q = 0; q < 4; q++) {
        int idx = t * 4 + q;
        int nb_l = idx >> 6, rem = idx & 63;
        int lane = rem >> 1, j = rem & 1;
        int group = lane >> 2, tig = lane & 3;
        int kp_l = tig + 4 * j;
        int n_l = nb_l * 8 + group;
        uint32_t h, l;
        cvt_pair(s[2*kp_l][n_l], s[2*kp_l + 1][n_l], h, l);
        long long o = ((long long)(kb * Nt8 + blockIdx.x * 16 + nb_l) * 32 + lane) * 2 + j;
        Hz[o] = h; Lz[o] = l;
    }
}

// ---------------- frag-layout GEMM (128x128 tile, 256 thr) ----------------
// A [K/16][Mtiles][32][4], B [K/16][Ntiles8][32][2]. bf16x3 emulation.
// PACKOUT=0: Cf fp32 [m][ldc] (+bias, relu). PACKOUT=1: CH/CL A-frag layout for next GEMM.
static const int SM_FR = 3 * 8192 * 4;   // 98,304 B

template<int PACKOUT>
__global__ __launch_bounds__(256)
void gemm_fr(const uint32_t* __restrict__ AH, const uint32_t* __restrict__ AL,
             const uint32_t* __restrict__ BH, const uint32_t* __restrict__ BL,
             const float* __restrict__ bias, float* __restrict__ Cf,
             uint32_t* __restrict__ CH, uint32_t* __restrict__ CL,
             int K, int Mtiles, int Ntiles8, int ldc, int outMtiles, int doRelu)
{
    extern __shared__ uint32_t smem[];
    int t = threadIdx.x;
    int wid = t >> 5, lane = t & 31;
    int wm = wid & 3, wn = wid >> 2;          // 4 x 2 warps
    int group = lane >> 2, tig = lane & 3;
    int mt0 = blockIdx.x * 8;                 // 8 m16-tiles per block
    int nb0 = blockIdx.y * 16;                // 16 n8-tiles per block
    int row0 = blockIdx.x * 128, col0 = blockIdx.y * 128;
    int nch = K >> 5;                         // 32-K chunks (2 kblks each)

    auto cpStage = [&](int c, int st) {
        uint32_t base = (uint32_t)__cvta_generic_to_shared(smem + st * 8192);
#pragma unroll
        for (int kb_l = 0; kb_l < 2; kb_l++) {
            int kb = c * 2 + kb_l;
            long long ga = ((long long)kb * Mtiles + mt0) * 128 + t * 4;
            long long gb = ((long long)kb * Ntiles8 + nb0) * 64 + t * 4;
            uint32_t so = (kb_l * 1024 + t * 4) * 4;
            cp_async16(base + so,            AH + ga);
            cp_async16(base + 2048*4 + so,   AL + ga);
            cp_async16(base + 4096*4 + so,   BH + gb);
            cp_async16(base + 6144*4 + so,   BL + gb);
        }
        CP_COMMIT();
    };

    float acc[2][8][4];
#pragma unroll
    for (int mt = 0; mt < 2; mt++)
#pragma unroll
        for (int nt = 0; nt < 8; nt++)
#pragma unroll
            for (int q = 0; q < 4; q++) acc[mt][nt][q] = 0.f;

    int pref = 0;
#pragma unroll
    for (int s = 0; s < 2; s++) { cpStage(pref, s); pref++; }

    int st = 0;
    for (int c = 0; c < nch; c++) {
        if (pref < nch) { cpStage(pref, pref % 3); pref++; }
        cp_wait_n(pref - c - 1);
        __syncthreads();
        const uint32_t* Ahs = smem + st * 8192;
        const uint32_t* Als = Ahs + 2048;
        const uint32_t* Bhs = Ahs + 4096;
        const uint32_t* Bls = Ahs + 6144;
#pragma unroll
        for (int ks = 0; ks < 2; ks++) {
            uint4 afh[2], afl[2];
            uint2 bfh[8], bfl[8];
#pragma unroll
            for (int mt = 0; mt < 2; mt++) {
                int off = ks * 1024 + (wm * 2 + mt) * 128 + lane * 4;
                afh[mt] = *reinterpret_cast<const uint4*>(Ahs + off);
                afl[mt] = *reinterpret_cast<const uint4*>(Als + off);
            }
#pragma unroll
            for (int nt = 0; nt < 8; nt++) {
                int off = ks * 1024 + (wn * 8 + nt) * 64 + lane * 2;
                bfh[nt] = *reinterpret_cast<const uint2*>(Bhs + off);
                bfl[nt] = *reinterpret_cast<const uint2*>(Bls + off);
            }
            // term-major (independent mmas between accumulator reuse)
#pragma unroll
            for (int mt = 0; mt < 2; mt++)
#pragma unroll
                for (int nt = 0; nt < 8; nt++)
                    mma16816(acc[mt][nt], reinterpret_cast<const uint32_t*>(&afh[mt]),
                             reinterpret_cast<const uint32_t*>(&bfh[nt]));
#pragma unroll
            for (int mt = 0; mt < 2; mt++)
#pragma unroll
                for (int nt = 0; nt < 8; nt++)
                    mma16816(acc[mt][nt], reinterpret_cast<const uint32_t*>(&afl[mt]),
                             reinterpret_cast<const uint32_t*>(&bfh[nt]));
#pragma unroll
            for (int mt = 0; mt < 2; mt++)
#pragma unroll
                for (int nt = 0; nt < 8; nt++)
                    mma16816(acc[mt][nt], reinterpret_cast<const uint32_t*>(&afh[mt]),
                             reinterpret_cast<const uint32_t*>(&bfl[nt]));
        }
        __syncthreads();
        if (++st == 3) st = 0;
    }

#pragma unroll
    for (int mt = 0; mt < 2; mt++) {
        int r = row0 + wm * 32 + mt * 16 + group;
#pragma unroll
        for (int nt = 0; nt < 8; nt++) {
            int c = col0 + wn * 64 + nt * 8 + tig * 2;
            float2 bb = *reinterpret_cast<const float2*>(&bias[c]);
            float v00 = acc[mt][nt][0] + bb.x;
            float v01 = acc[mt][nt][1] + bb.y;
            float v10 = acc[mt][nt][2] + bb.x;
            float v11 = acc[mt][nt][3] + bb.y;
            if (doRelu) {
                v00 = fmaxf(v00, 0.f); v01 = fmaxf(v01, 0.f);
                v10 = fmaxf(v10, 0.f); v11 = fmaxf(v11, 0.f);
            }
            if (PACKOUT == 0) {
                *reinterpret_cast<float2*>(&Cf[(long long)r * ldc + c])       = make_float2(v00, v01);
                *reinterpret_cast<float2*>(&Cf[(long long)(r + 8) * ldc + c]) = make_float2(v10, v11);
            } else {
                int kp = c >> 1;
                int kb2 = kp >> 3;
                int j0 = ((kp >> 2) & 1) * 2;
                int mt2 = r >> 4;
                long long base = ((long long)(kb2 * outMtiles + mt2) * 32 + lane) * 4 + j0;
                uint32_t h, l;
                cvt_pair(v00, v01, h, l); CH[base] = h;     CL[base] = l;
                cvt_pair(v10, v11, h, l); CH[base + 1] = h; CL[base + 1] = l;
            }
        }
    }
}

// ---------------- all-packed mma.sync GEMM (64-tile; MHA path) ----------------
template<int TBM, int TBN, int NTHREADS, int WARPS_M, int STAGES, int PACKMODE>
__global__ __launch_bounds__(NTHREADS)
void gemm_ap(const uint32_t* __restrict__ AH, const uint32_t* __restrict__ AL,
             const uint32_t* __restrict__ BH, const uint32_t* __restrict__ BL,
             const float* __restrict__ bias, float* __restrict__ C,
             uint32_t* __restrict__ CH, uint32_t* __restrict__ CL,
             int K, int ldap, int ldbp, int ldc, int ldc2,
             long long sAo, long long sAi, long long sBo, long long sBi,
             long long sCo, long long sCi, int Hsub, int rThresh,
             float alpha, int doBias, int doRelu)
{
    constexpr int WARPS   = NTHREADS / 32;
    constexpr int WARPS_N = WARPS / WARPS_M;
    constexpr int WM = TBM / WARPS_M;
    constexpr int WN = TBN / WARPS_N;
    constexpr int MT = WM / 16;
    constexpr int NT = WN / 8;
    constexpr int AS = TBM + 8;
    constexpr int BS = TBN + 8;
    constexpr int ASZ = 16 * AS;
    constexpr int BSZ = 16 * BS;
    constexpr int AC = (16 * (TBM / 4)) / NTHREADS;
    constexpr int BC = (16 * (TBN / 4)) / NTHREADS;

    extern __shared__ uint32_t smem[];
    uint32_t* sAh = smem;
    uint32_t* sAl = smem + STAGES * ASZ;
    uint32_t* sBh = smem + 2 * STAGES * ASZ;
    uint32_t* sBl = smem + 2 * STAGES * ASZ + STAGES * BSZ;

    int z = blockIdx.z;
    int zo = z / Hsub, zi = z % Hsub;
    const uint32_t* Ahb = AH + zo * sAo + zi * sAi;
    const uint32_t* Alb = AL + zo * sAo + zi * sAi;
    const uint32_t* Bhb = BH + zo * sBo + zi * sBi;
    const uint32_t* Blb = BL + zo * sBo + zi * sBi;
    float*    Cb  = (PACKMODE == 0) ? (C + zo * sCo + zi * sCi) : nullptr;
    uint32_t* CHb = (PACKMODE != 0) ? (CH + zo * sCo + zi * sCi) : nullptr;
    uint32_t* CLb = (PACKMODE != 0) ? (CL + zo * sCo + zi * sCi) : nullptr;

    int tid = threadIdx.x;
    int wid = tid >> 5, lane = tid & 31;
    int wm = wid % WARPS_M, wn = wid / WARPS_M;
    int group = lane >> 2, tig = lane & 3;
    int row0 = blockIdx.x * TBM;
    int col0 = blockIdx.y * TBN;

    auto cpStage = [&](int k0, int st) {
        int kp0 = k0 >> 1;
        uint32_t ah0 = (uint32_t)__cvta_generic_to_shared(sAh + st * ASZ);
        uint32_t al0 = (uint32_t)__cvta_generic_to_shared(sAl + st * ASZ);
#pragma unroll
        for (int j = 0; j < AC; j++) {
            int ci = tid + j * NTHREADS;
            int rr = ci / (TBM / 4), cc = ci % (TBM / 4);
            long long go = (long long)(kp0 + rr) * ldap + row0 + cc * 4;
            uint32_t so = (rr * AS + cc * 4) * 4;
            cp_async16(ah0 + so, Ahb + go);
            cp_async16(al0 + so, Alb + go);
        }
        uint32_t bh0 = (uint32_t)__cvta_generic_to_shared(sBh + st * BSZ);
        uint32_t bl0 = (uint32_t)__cvta_generic_to_shared(sBl + st * BSZ);
#pragma unroll
        for (int j = 0; j < BC; j++) {
            int ci = tid + j * NTHREADS;
            int rr = ci / (TBN / 4), cc = ci % (TBN / 4);
            long long go = (long long)(kp0 + rr) * ldbp + col0 + cc * 4;
            uint32_t so = (rr * BS + cc * 4) * 4;
            cp_async16(bh0 + so, Bhb + go);
            cp_async16(bl0 + so, Blb + go);
        }
        CP_COMMIT();
    };

    float acc[MT][NT][4];
#pragma unroll
    for (int i = 0; i < MT; i++)
#pragma unroll
        for (int j = 0; j < NT; j++)
#pragma unroll
            for (int t = 0; t < 4; t++) acc[i][j][t] = 0.f;

    int kpref = 0;
#pragma unroll
    for (int s = 0; s < STAGES - 1; s++) { cpStage(kpref, s); kpref += 32; }

    int st = 0;
    for (int k0 = 0; k0 < K; k0 += 32) {
        if (kpref < K) {
            cpStage(kpref, (kpref >> 5) % STAGES);
            kpref += 32;
        }
        cp_wait_n(((kpref - k0) >> 5) - 1);
        __syncthreads();

        const uint32_t* Ahs = sAh + st * ASZ;
        const uint32_t* Als = sAl + st * ASZ;
        const uint32_t* Bhs = sBh + st * BSZ;
        const uint32_t* Bls = sBl + st * BSZ;
#pragma unroll
        for (int ks = 0; ks < 2; ks++) {
            uint32_t ah[MT][4], al[MT][4], bh[NT][2], bl[NT][2];
            int kp0 = ks * 8 + tig, kp1 = kp0 + 4;
#pragma unroll
            for (int mt = 0; mt < MT; mt++) {
                int r = wm * WM + mt * 16 + group;
                ah[mt][0] = Ahs[kp0 * AS + r];     al[mt][0] = Als[kp0 * AS + r];
                ah[mt][1] = Ahs[kp0 * AS + r + 8]; al[mt][1] = Als[kp0 * AS + r + 8];
                ah[mt][2] = Ahs[kp1 * AS + r];     al[mt][2] = Als[kp1 * AS + r];
                ah[mt][3] = Ahs[kp1 * AS + r + 8]; al[mt][3] = Als[kp1 * AS + r + 8];
            }
#pragma unroll
            for (int nt = 0; nt < NT; nt++) {
                int c = wn * WN + nt * 8 + group;
                bh[nt][0] = Bhs[kp0 * BS + c];  bl[nt][0] = Bls[kp0 * BS + c];
                bh[nt][1] = Bhs[kp1 * BS + c];  bl[nt][1] = Bls[kp1 * BS + c];
            }
#pragma unroll
            for (int mt = 0; mt < MT; mt++)
#pragma unroll
                for (int nt = 0; nt < NT; nt++)
                    mma16816(acc[mt][nt], ah[mt], bh[nt]);
#pragma unroll
            for (int mt = 0; mt < MT; mt++)
#pragma unroll
                for (int nt = 0; nt < NT; nt++)
                    mma16816(acc[mt][nt], al[mt], bh[nt]);
#pragma unroll
            for (int mt = 0; mt < MT; mt++)
#pragma unroll
                for (int nt = 0; nt < NT; nt++)
                    mma16816(acc[mt][nt], ah[mt], bl[nt]);
        }
        __syncthreads();
        if (++st == STAGES) st = 0;
    }

    int effMode = (PACKMODE == 3) ? ((zi >= rThresh) ? 2 : 1) : PACKMODE;

#pragma unroll
    for (int mt = 0; mt < MT; mt++) {
        int r = row0 + wm * WM + mt * 16 + group;
#pragma unroll
        for (int nt = 0; nt < NT; nt++) {
            int c = col0 + wn * WN + nt * 8 + tig * 2;
            float v00 = acc[mt][nt][0] * alpha;
            float v01 = acc[mt][nt][1] * alpha;
            float v10 = acc[mt][nt][2] * alpha;
            float v11 = acc[mt][nt][3] * alpha;
            if (doBias) {
                float2 bb = *reinterpret_cast<const float2*>(&bias[c]);
                v00 += bb.x; v01 += bb.y; v10 += bb.x; v11 += bb.y;
            }
            if (doRelu) {
                v00 = fmaxf(v00, 0.f); v01 = fmaxf(v01, 0.f);
                v10 = fmaxf(v10, 0.f); v11 = fmaxf(v11, 0.f);
            }
            if (PACKMODE == 0) {
                *reinterpret_cast<float2*>(&Cb[(long long)r * ldc + c])       = make_float2(v00, v01);
                *reinterpret_cast<float2*>(&Cb[(long long)(r + 8) * ldc + c]) = make_float2(v10, v11);
            } else if (effMode == 1) {
                long long base = (long long)(c >> 1) * ldc + r;
                uint32_t h, l;
                cvt_pair(v00, v01, h, l); CHb[base] = h;     CLb[base] = l;
                cvt_pair(v10, v11, h, l); CHb[base + 8] = h; CLb[base + 8] = l;
            } else {
                float u00 = __shfl_down_sync(0xffffffffu, v00, 4);
                float u01 = __shfl_down_sync(0xffffffffu, v01, 4);
                float u10 = __shfl_down_sync(0xffffffffu, v10, 4);
                float u11 = __shfl_down_sync(0xffffffffu, v11, 4);
                if (!(group & 1)) {
                    long long b0 = (long long)(r >> 1) * ldc2 + c;
                    long long b8 = (long long)((r + 8) >> 1) * ldc2 + c;
                    uint32_t h, l;
                    cvt_pair(v00, u00, h, l); CHb[b0]     = h; CLb[b0]     = l;
                    cvt_pair(v01, u01, h, l); CHb[b0 + 1] = h; CLb[b0 + 1] = l;
                    cvt_pair(v10, u10, h, l); CHb[b8]     = h; CLb[b8]     = l;
                    cvt_pair(v11, u11, h, l); CHb[b8 + 1] = h; CLb[b8 + 1] = l;
                }
            }
        }
    }
}

// ---------------- fused flash attention ----------------
#define FA_STRIDE 68
#define FA_TSZ (32 * FA_STRIDE)
__global__ __launch_bounds__(128)
void flash_attn(const uint32_t* __restrict__ Qh, const uint32_t* __restrict__ Ql,
                const uint32_t* __restrict__ Kh, const uint32_t* __restrict__ Kl,
                const uint32_t* __restrict__ Vh, const uint32_t* __restrict__ Vl,
                uint32_t* __restrict__ Oh, uint32_t* __restrict__ Ol, int causal)
{
    extern __shared__ uint32_t smem[];
    uint32_t* sKh = smem;
    uint32_t* sKl = smem + 2 * FA_TSZ;
    uint32_t* sVh = smem + 4 * FA_TSZ;
    uint32_t* sVl = smem + 6 * FA_TSZ;

    int qb = blockIdx.x;
    int b  = blockIdx.y / Hh;
    int h  = blockIdx.y % Hh;
    int tid = threadIdx.x;
    int wid = tid >> 5, lane = tid & 31;
    int group = lane >> 2, tig = lane & 3;
    int tokBase = b * Ss + qb * 64 + wid * 16;

    uint32_t qh[4][4], ql[4][4];
    const uint32_t SC = 0x3E003E00u;
#pragma unroll
    for (int ks = 0; ks < 4; ks++) {
        int kpa = h * 32 + ks * 8 + tig;
        long long b0 = (long long)kpa * TOK + tokBase + group;
        long long b2 = (long long)(kpa + 4) * TOK + tokBase + group;
        qh[ks][0] = mulbf2(Qh[b0], SC);     ql[ks][0] = mulbf2(Ql[b0], SC);
        qh[ks][1] = mulbf2(Qh[b0 + 8], SC); ql[ks][1] = mulbf2(Ql[b0 + 8], SC);
        qh[ks][2] = mulbf2(Qh[b2], SC);     ql[ks][2] = mulbf2(Ql[b2], SC);
        qh[ks][3] = mulbf2(Qh[b2 + 8], SC); ql[ks][3] = mulbf2(Ql[b2 + 8], SC);
    }

    float m0 = -INFINITY, m1 = -INFINITY, l0 = 0.f, l1 = 0.f;
    float acc_o[8][4];
#pragma unroll
    for (int nt = 0; nt < 8; nt++)
#pragma unroll
        for (int t = 0; t < 4; t++) acc_o[nt][t] = 0.f;

    int nkb = causal ? (qb + 1) : (Ss / 64);

    auto cpStage = [&](int kb, int stg) {
        uint32_t kh0 = (uint32_t)__cvta_generic_to_shared(sKh + stg * FA_TSZ);
        uint32_t kl0 = (uint32_t)__cvta_generic_to_shared(sKl + stg * FA_TSZ);
        uint32_t vh0 = (uint32_t)__cvta_generic_to_shared(sVh + stg * FA_TSZ);
        uint32_t vl0 = (uint32_t)__cvta_generic_to_shared(sVl + stg * FA_TSZ);
#pragma unroll
        for (int i = 0; i < 4; i++) {
            int idx = tid + i * 128;
            int row = idx >> 4, c4 = idx & 15;
            uint32_t so = (row * FA_STRIDE + c4 * 4) * 4;
            long long gK = (long long)(h * 32 + row) * TOK + b * Ss + kb * 64 + c4 * 4;
            cp_async16(kh0 + so, Kh + gK);
            cp_async16(kl0 + so, Kl + gK);
            long long gV = (long long)(b * (Ss / 2) + kb * 32 + row) * Dd + h * 64 + c4 * 4;
            cp_async16(vh0 + so, Vh + gV);
            cp_async16(vl0 + so, Vl + gV);
        }
        CP_COMMIT();
    };

    cpStage(0, 0);
    for (int kb = 0; kb < nkb; kb++) {
        if (kb + 1 < nkb) {
            cpStage(kb + 1, (kb + 1) & 1);
            asm volatile("cp.async.wait_group 1;");
        } else {
            asm volatile("cp.async.wait_group 0;");
        }
        __syncthreads();
        int stg = kb & 1;
        const uint32_t* Ksh = sKh + stg * FA_TSZ;
        const uint32_t* Ksl = sKl + stg * FA_TSZ;
        const uint32_t* Vsh = sVh + stg * FA_TSZ;
        const uint32_t* Vsl = sVl + stg * FA_TSZ;

        float s[8][4];
#pragma unroll
        for (int nt = 0; nt < 8; nt++)
#pragma unroll
            for (int t = 0; t < 4; t++) s[nt][t] = 0.f;
#pragma unroll
        for (int ks = 0; ks < 4; ks++) {
            int r0 = (ks * 8 + tig) * FA_STRIDE, r1 = r0 + 4 * FA_STRIDE;
            uint32_t bhf[8][2], blf[8][2];
#pragma unroll
            for (int nt = 0; nt < 8; nt++) {
                int c = nt * 8 + group;
                bhf[nt][0] = Ksh[r0 + c]; bhf[nt][1] = Ksh[r1 + c];
                blf[nt][0] = Ksl[r0 + c]; blf[nt][1] = Ksl[r1 + c];
            }
#pragma unroll
            for (int nt = 0; nt < 8; nt++) mma16816(s[nt], qh[ks], bhf[nt]);
#pragma unroll
            for (int nt = 0; nt < 8; nt++) mma16816(s[nt], ql[ks], bhf[nt]);
#pragma unroll
            for (int nt = 0; nt < 8; nt++) mma16816(s[nt], qh[ks], blf[nt]);
        }

        if (causal && kb == qb) {
            int r0 = wid * 16 + group, r1 = r0 + 8;
#pragma unroll
            for (int nt = 0; nt < 8; nt++) {
                int c0 = nt * 8 + tig * 2;
                if (c0     > r0) s[nt][0] = -1e9f;
                if (c0 + 1 > r0) s[nt][1] = -1e9f;
                if (c0     > r1) s[nt][2] = -1e9f;
                if (c0 + 1 > r1) s[nt][3] = -1e9f;
            }
        }

        float bm0 = -INFINITY, bm1 = -INFINITY;
#pragma unroll
        for (int nt = 0; nt < 8; nt++) {
            bm0 = fmaxf(bm0, fmaxf(s[nt][0], s[nt][1]));
            bm1 = fmaxf(bm1, fmaxf(s[nt][2], s[nt][3]));
        }
        bm0 = fmaxf(bm0, __shfl_xor_sync(0xffffffffu, bm0, 1));
        bm0 = fmaxf(bm0, __shfl_xor_sync(0xffffffffu, bm0, 2));
        bm1 = fmaxf(bm1, __shfl_xor_sync(0xffffffffu, bm1, 1));
        bm1 = fmaxf(bm1, __shfl_xor_sync(0xffffffffu, bm1, 2));
        float nm0 = fmaxf(m0, bm0), nm1 = fmaxf(m1, bm1);
        float a0f = __expf(m0 - nm0), a1f = __expf(m1 - nm1);
        m0 = nm0; m1 = nm1;
        float rs0 = 0.f, rs1 = 0.f;
#pragma unroll
        for (int nt = 0; nt < 8; nt++) {
            s[nt][0] = __expf(s[nt][0] - nm0);
            s[nt][1] = __expf(s[nt][1] - nm0);
            s[nt][2] = __expf(s[nt][2] - nm1);
            s[nt][3] = __expf(s[nt][3] - nm1);
            rs0 += s[nt][0] + s[nt][1];
            rs1 += s[nt][2] + s[nt][3];
        }
        rs0 += __shfl_xor_sync(0xffffffffu, rs0, 1);
        rs0 += __shfl_xor_sync(0xffffffffu, rs0, 2);
        rs1 += __shfl_xor_sync(0xffffffffu, rs1, 1);
        rs1 += __shfl_xor_sync(0xffffffffu, rs1, 2);
        l0 = l0 * a0f + rs0;
        l1 = l1 * a1f + rs1;
#pragma unroll
        for (int nt = 0; nt < 8; nt++) {
            acc_o[nt][0] *= a0f; acc_o[nt][1] *= a0f;
            acc_o[nt][2] *= a1f; acc_o[nt][3] *= a1f;
        }

        uint32_t ph[4][4], pl[4][4];
#pragma unroll
        for (int j = 0; j < 4; j++) {
            cvt_pair(s[2*j  ][0], s[2*j  ][1], ph[j][0], pl[j][0]);
            cvt_pair(s[2*j  ][2], s[2*j  ][3], ph[j][1], pl[j][1]);
            cvt_pair(s[2*j+1][0], s[2*j+1][1], ph[j][2], pl[j][2]);
            cvt_pair(s[2*j+1][2], s[2*j+1][3], ph[j][3], pl[j][3]);
        }

#pragma unroll
        for (int j = 0; j < 4; j++) {
            int r0 = (j * 8 + tig) * FA_STRIDE, r1 = r0 + 4 * FA_STRIDE;
            uint32_t vbh[8][2], vbl[8][2];
#pragma unroll
            for (int nt = 0; nt < 8; nt++) {
                int c = nt * 8 + group;
                vbh[nt][0] = Vsh[r0 + c]; vbh[nt][1] = Vsh[r1 + c];
                vbl[nt][0] = Vsl[r0 + c]; vbl[nt][1] = Vsl[r1 + c];
            }
#pragma unroll
            for (int nt = 0; nt < 8; nt++) mma16816(acc_o[nt], ph[j], vbh[nt]);
#pragma unroll
            for (int nt = 0; nt < 8; nt++) mma16816(acc_o[nt], pl[j], vbh[nt]);
#pragma unroll
            for (int nt = 0; nt < 8; nt++) mma16816(acc_o[nt], ph[j], vbl[nt]);
        }
        __syncthreads();
    }

    float inv0 = 1.0f / l0, inv1 = 1.0f / l1;
#pragma unroll
    for (int nt = 0; nt < 8; nt++) {
        int cp = h * 32 + nt * 4 + tig;
        long long bo = (long long)cp * TOK + tokBase + group;
        uint32_t hh, ll;
        cvt_pair(acc_o[nt][0] * inv0, acc_o[nt][1] * inv0, hh, ll);
        Oh[bo] = hh; Ol[bo] = ll;
        cvt_pair(acc_o[nt][2] * inv1, acc_o[nt][3] * inv1, hh, ll);
        Oh[bo + 8] = hh; Ol[bo + 8] = ll;
    }
}

// ---------------- vocab softmax ----------
__global__ __launch_bounds__(1024)
void softmax_vocab(float* __restrict__ P)
{
    float* p = P + (long long)blockIdx.x * Vv;
    int t = threadIdx.x;
    __shared__ float red[32];
    float v[32];
    float mx = -3.0e38f;
#pragma unroll
    for (int i = 0; i < 32; i++) {
        int idx = t + i * 1024;
        v[i] = (idx < Vv) ? p[idx] : -3.0e38f;
        mx = fmaxf(mx, v[i]);
    }
    for (int o = 16; o; o >>= 1) mx = fmaxf(mx, __shfl_xor_sync(0xffffffffu, mx, o));
    if ((t & 31) == 0) red[t >> 5] = mx;
    __syncthreads();
    if (t < 32) {
        float m2 = red[t];
        for (int o = 16; o; o >>= 1) m2 = fmaxf(m2, __shfl_xor_sync(0xffffffffu, m2, o));
        if (t == 0) red[0] = m2;
    }
    __syncthreads();
    mx = red[0];
    __syncthreads();
    float sum = 0.f;
#pragma unroll
    for (int i = 0; i < 32; i++) { v[i] = __expf(v[i] - mx); sum += v[i]; }
    for (int o = 16; o; o >>= 1) sum += __shfl_xor_sync(0xffffffffu, sum, o);
    if ((t & 31) == 0) red[t >> 5] = sum;
    __syncthreads();
    if (t < 32) {
        float s2 = red[t];
        for (int o = 16; o; o >>= 1) s2 += __shfl_xor_sync(0xffffffffu, s2, o);
        if (t == 0) red[0] = s2;
    }
    __syncthreads();
    float inv = 1.0f / red[0];
#pragma unroll
    for (int i = 0; i < 32; i++) {
        int idx = t + i * 1024;
        if (idx < Vv) p[idx] = v[i] * inv;
    }
}

// ---------------- add + LayerNorm ----------
__global__ __launch_bounds__(256)
void add_ln_kernel(float* __restrict__ x, const float* __restrict__ sub)
{
    int row = blockIdx.x;
    float* xr = x + (long long)row * Dd;
    const float* sr = sub + (long long)row * Dd;
    int t = threadIdx.x;
    __shared__ float red[256];

    float v0 = xr[t] + sr[t];
    float v1 = xr[t + 256] + sr[t + 256];
    red[t] = v0 + v1; __syncthreads();
    for (int o = 128; o; o >>= 1) { if (t < o) red[t] += red[t + o]; __syncthreads(); }
    float mu = red[0] * (1.0f / 512.0f); __syncthreads();
    float d0 = v0 - mu, d1 = v1 - mu;
    red[t] = d0 * d0 + d1 * d1; __syncthreads();
    for (int o = 128; o; o >>= 1) { if (t < o) red[t] += red[t + o]; __syncthreads(); }
    float inv = rsqrtf(red[0] * (1.0f / 512.0f) + 1e-5f);
    xr[t] = d0 * inv;
    xr[t + 256] = d1 * inv;
}

// ---------------- embedding + PE ----------
__global__ __launch_bounds__(512)
void embed_pe_kernel(const int* __restrict__ tok, const float* __restrict__ emb,
                     float* __restrict__ out)
{
    int idx = blockIdx.x;
    int s = idx % Ss;
    int j = threadIdx.x;
    int tk = tok[idx];
    float ang = (float)s * powf(10000.0f, -2.0f * (float)j / 512.0f);
    float pe = (j & 1) ? cosf(ang) : sinf(ang);
    out[(long long)idx * Dd + j] = emb[(long long)tk * Dd + j] + pe;
}

// ---------------- host ----------------
static const int SM_AP64_3  = (4 * 3 * 16 * (64 + 8)) * 4;     // 55,296
static const int SM_FA      = 8 * FA_TSZ * 4;                  // 69,632

struct GPtrs {
    float *x, *y, *tmp;
    uint32_t *encWh, *encWl, *decSWh, *decSWl, *decCWh, *decCWl;
    uint32_t *eW1h, *eW1l, *eW2h, *eW2l, *dW1h, *dW1l, *dW2h, *dW2l;
    uint32_t *oWh, *oWl;
    uint32_t *xTh, *xTl, *qkvPh, *qkvPl, *oTh, *oTl, *xeTh, *xeTl, *xKVh, *xKVl, *fTh, *fTl;
};

static void run_mha_self(GPtrs& G, const float* xq,
                         const uint32_t* wh, const uint32_t* wl, float* out, bool causal)
{
    convAT<<<dim3(TOK/32, Dd/32), 256>>>(xq, G.xTh, G.xTl, TOK, Dd);
    {
        dim3 g(TOK/64, Dd/64, 3);
        gemm_ap<64,64,128,2,3,3><<<g, 128, SM_AP64_3>>>(G.xTh, G.xTl, wh, wl,
            nullptr, nullptr, G.qkvPh, G.qkvPl,
            Dd, TOK, Dd, TOK, Dd,
            0, 0, 0, DD2, 0, KVC, 3, 2, 1.0f, 0, 0);
    }
    flash_attn<<<dim3(Ss/64, Bn*Hh), 128, SM_FA>>>(
        G.qkvPh, G.qkvPl, G.qkvPh + KVC, G.qkvPl + KVC,
        G.qkvPh + 2*KVC, G.qkvPl + 2*KVC, G.oTh, G.oTl, causal ? 1 : 0);
    {
        dim3 g(TOK/64, Dd/64, 1);
        gemm_ap<64,64,128,2,3,0><<<g, 128, SM_AP64_3>>>(G.oTh, G.oTl, wh + 3*DD2, wl + 3*DD2,
            nullptr, out, nullptr, nullptr,
            Dd, TOK, Dd, Dd, Dd,
            0, 0, 0, 0, 0, 0, 1, 0, 1.0f, 0, 0);
    }
}

static void run_mha_cross(GPtrs& G, const float* yq, int layer,
                          const uint32_t* wh, const uint32_t* wl, float* out)
{
    convAT<<<dim3(TOK/32, Dd/32), 256>>>(yq, G.xTh, G.xTl, TOK, Dd);
    {
        dim3 g(TOK/64, Dd/64, 1);
        gemm_ap<64,64,128,2,3,1><<<g, 128, SM_AP64_3>>>(G.xTh, G.xTl, wh, wl,
            nullptr, nullptr, G.qkvPh, G.qkvPl,
            Dd, TOK, Dd, TOK, Dd,
            0, 0, 0, 0, 0, 0, 1, 0, 1.0f, 0, 0);
    }
    const uint32_t* kh = G.xKVh + (long long)layer * 2 * KVC;
    const uint32_t* kl = G.xKVl + (long long)layer * 2 * KVC;
    flash_attn<<<dim3(Ss/64, Bn*Hh), 128, SM_FA>>>(
        G.qkvPh, G.qkvPl, kh, kl, kh + KVC, kl + KVC, G.oTh, G.oTl, 0);
    {
        dim3 g(TOK/64, Dd/64, 1);
        gemm_ap<64,64,128,2,3,0><<<g, 128, SM_AP64_3>>>(G.oTh, G.oTl, wh + 3*DD2, wl + 3*DD2,
            nullptr, out, nullptr, nullptr,
            Dd, TOK, Dd, Dd, Dd,
            0, 0, 0, 0, 0, 0, 1, 0, 1.0f, 0, 0);
    }
}

static void run_ffn(GPtrs& G, float* xact, const uint32_t* w1h, const uint32_t* w1l,
                    const float* b1, const uint32_t* w2h, const uint32_t* w2l, const float* b2)
{
    // pack activation to frag layout [Dd/16][TOK/16][32][4]
    convAF<<<dim3(TOK/128, Dd/16), 256>>>(xact, G.xTh, G.xTl, Dd, TOK/16);
    // FFN1: frag GEMM, output packed directly in frag layout for FFN2
    gemm_fr<1><<<dim3(TOK/128, FFf/128), 256, SM_FR>>>(G.xTh, G.xTl, w1h, w1l,
        b1, nullptr, G.fTh, G.fTl, Dd, TOK/16, FFf/8, 0, TOK/16, 1);
    // FFN2: frag GEMM, fp32 out + bias
    gemm_fr<0><<<dim3(TOK/128, Dd/128), 256, SM_FR>>>(G.fTh, G.fTl, w2h, w2l,
        b2, G.tmp, nullptr, nullptr, FFf, TOK/16, Dd/8, Dd, 0, 0);
}

extern "C" void kernel_launch(void* const* d_in, const int* in_sizes, int n_in,
                              void* d_out, int out_size)
{
    const int*   src           = (const int*)  d_in[0];
    const int*   trg           = (const int*)  d_in[1];
    const float* src_emb       = (const float*)d_in[2];
    const float* trg_emb       = (const float*)d_in[3];
    const float* enc_qkvo      = (const float*)d_in[4];
    const float* enc_ffn_w1    = (const float*)d_in[5];
    const float* enc_ffn_b1    = (const float*)d_in[6];
    const float* enc_ffn_w2    = (const float*)d_in[7];
    const float* enc_ffn_b2    = (const float*)d_in[8];
    const float* dec_self_qkvo = (const float*)d_in[9];
    const float* dec_cross_qkvo= (const float*)d_in[10];
    const float* dec_ffn_w1    = (const float*)d_in[11];
    const float* dec_ffn_b1    = (const float*)d_in[12];
    const float* dec_ffn_w2    = (const float*)d_in[13];
    const float* dec_ffn_b2    = (const float*)d_in[14];
    const float* out_w         = (const float*)d_in[15];
    const float* out_b         = (const float*)d_in[16];
    float* out = (float*)d_out;

    cudaFuncSetAttribute(gemm_ap<64,64,128,2,3,0>,
                         cudaFuncAttributeMaxDynamicSharedMemorySize, SM_AP64_3);
    cudaFuncSetAttribute(gemm_ap<64,64,128,2,3,1>,
                         cudaFuncAttributeMaxDynamicSharedMemorySize, SM_AP64_3);
    cudaFuncSetAttribute(gemm_ap<64,64,128,2,3,3>,
                         cudaFuncAttributeMaxDynamicSharedMemorySize, SM_AP64_3);
    cudaFuncSetAttribute(flash_attn,
                         cudaFuncAttributeMaxDynamicSharedMemorySize, SM_FA);
    cudaFuncSetAttribute(gemm_fr<0>,
                         cudaFuncAttributeMaxDynamicSharedMemorySize, SM_FR);
    cudaFuncSetAttribute(gemm_fr<1>,
                         cudaFuncAttributeMaxDynamicSharedMemorySize, SM_FR);

    GPtrs G;
    cudaGetSymbolAddress((void**)&G.x,    g_x);
    cudaGetSymbolAddress((void**)&G.y,    g_y);
    cudaGetSymbolAddress((void**)&G.tmp,  g_tmp);
    cudaGetSymbolAddress((void**)&G.encWh,  g_encW_h);  cudaGetSymbolAddress((void**)&G.encWl, g_encW_l);
    cudaGetSymbolAddress((void**)&G.decSWh, g_decSW_h); cudaGetSymbolAddress((void**)&G.decSWl, g_decSW_l);
    cudaGetSymbolAddress((void**)&G.decCWh, g_decCW_h); cudaGetSymbolAddress((void**)&G.decCWl, g_decCW_l);
    cudaGetSymbolAddress((void**)&G.eW1h,   g_encW1_h); cudaGetSymbolAddress((void**)&G.eW1l, g_encW1_l);
    cudaGetSymbolAddress((void**)&G.eW2h,   g_encW2_h); cudaGetSymbolAddress((void**)&G.eW2l, g_encW2_l);
    cudaGetSymbolAddress((void**)&G.dW1h,   g_decW1_h); cudaGetSymbolAddress((void**)&G.dW1l, g_decW1_l);
    cudaGetSymbolAddress((void**)&G.dW2h,   g_decW2_h); cudaGetSymbolAddress((void**)&G.dW2l, g_decW2_l);
    cudaGetSymbolAddress((void**)&G.oWh,    g_outW_h);  cudaGetSymbolAddress((void**)&G.oWl, g_outW_l);
    cudaGetSymbolAddress((void**)&G.xTh,    g_xT_h);    cudaGetSymbolAddress((void**)&G.xTl, g_xT_l);
    cudaGetSymbolAddress((void**)&G.qkvPh,  g_qkvP_h);  cudaGetSymbolAddress((void**)&G.qkvPl, g_qkvP_l);
    cudaGetSymbolAddress((void**)&G.oTh,    g_oT_h);    cudaGetSymbolAddress((void**)&G.oTl, g_oT_l);
    cudaGetSymbolAddress((void**)&G.xeTh,   g_xeT_h);   cudaGetSymbolAddress((void**)&G.xeTl, g_xeT_l);
    cudaGetSymbolAddress((void**)&G.xKVh,   g_xKV_h);   cudaGetSymbolAddress((void**)&G.xKVl, g_xKV_l);
    cudaGetSymbolAddress((void**)&G.fTh,    g_fT_h);    cudaGetSymbolAddress((void**)&G.fTl, g_fT_l);

    // attention weight conversions (old [K/2][N] layout for gemm_ap)
    convB<<<dim3(Dd / 256,  24 * Dd / 2), 256>>>(enc_qkvo,       G.encWh, G.encWl, Dd);
    convB<<<dim3(Dd / 256,  24 * Dd / 2), 256>>>(dec_self_qkvo,  G.decSWh, G.decSWl, Dd);
    convB<<<dim3(Dd / 256,  24 * Dd / 2), 256>>>(dec_cross_qkvo, G.decCWh, G.decCWl, Dd);
    // FFN + vocab weights: fragment layout for gemm_fr
    convWF<<<dim3(FFf / 128, Dd / 16, Nl), 256>>>(enc_ffn_w1, G.eW1h, G.eW1l, Dd, FFf);
    convWF<<<dim3(Dd / 128,  FFf / 16, Nl), 256>>>(enc_ffn_w2, G.eW2h, G.eW2l, FFf, Dd);
    convWF<<<dim3(FFf / 128, Dd / 16, Nl), 256>>>(dec_ffn_w1, G.dW1h, G.dW1l, Dd, FFf);
    convWF<<<dim3(Dd / 128,  FFf / 16, Nl), 256>>>(dec_ffn_w2, G.dW2h, G.dW2l, FFf, Dd);
    convWF<<<dim3(Vv / 128,  Dd / 16, 1),  256>>>(out_w, G.oWh, G.oWl, Dd, Vv);

    embed_pe_kernel<<<TOK, 512>>>(src, src_emb, G.x);
    embed_pe_kernel<<<TOK, 512>>>(trg, trg_emb, G.y);

    // ---------------- Encoder ----------------
    for (int i = 0; i < Nl; i++) {
        run_mha_self(G, G.x,
                G.encWh + (long long)i * 4 * DD2, G.encWl + (long long)i * 4 * DD2,
                G.tmp, false);
        add_ln_kernel<<<TOK, 256>>>(G.x, G.tmp);
        run_ffn(G, G.x,
                G.eW1h + (long long)i * W1SZ, G.eW1l + (long long)i * W1SZ,
                enc_ffn_b1 + (long long)i * FFf,
                G.eW2h + (long long)i * W1SZ, G.eW2l + (long long)i * W1SZ,
                enc_ffn_b2 + (long long)i * Dd);
        add_ln_kernel<<<TOK, 256>>>(G.x, G.tmp);
    }

    // pack encoder output; precompute ALL cross-attn K,V (6 layers)
    convAT<<<dim3(TOK/32, Dd/32), 256>>>(G.x, G.xeTh, G.xeTl, TOK, Dd);
    {
        dim3 g(TOK/64, Dd/64, 2 * Nl);
        gemm_ap<64,64,128,2,3,3><<<g, 128, SM_AP64_3>>>(G.xeTh, G.xeTl,
            G.decCWh + DD2, G.decCWl + DD2,
            nullptr, nullptr, G.xKVh, G.xKVl,
            Dd, TOK, Dd, TOK, Dd,
            0, 0, (long long)4 * DD2, DD2, (long long)2 * KVC, KVC,
            2, 1, 1.0f, 0, 0);
    }

    // ---------------- Decoder ----------------
    for (int i = 0; i < Nl; i++) {
        run_mha_self(G, G.y,
                G.decSWh + (long long)i * 4 * DD2, G.decSWl + (long long)i * 4 * DD2,
                G.tmp, true);
        add_ln_kernel<<<TOK, 256>>>(G.y, G.tmp);

        run_mha_cross(G, G.y, i,
                G.decCWh + (long long)i * 4 * DD2, G.decCWl + (long long)i * 4 * DD2,
                G.tmp);
        add_ln_kernel<<<TOK, 256>>>(G.y, G.tmp);

        run_ffn(G, G.y,
                G.dW1h + (long long)i * W1SZ, G.dW1l + (long long)i * W1SZ,
                dec_ffn_b1 + (long long)i * FFf,
                G.dW2h + (long long)i * W1SZ, G.dW2l + (long long)i * W1SZ,
                dec_ffn_b2 + (long long)i * Dd);
        add_ln_kernel<<<TOK, 256>>>(G.y, G.tmp);
    }

    // ---------------- Output projection (frag GEMM) + vocab softmax ----------------
    convAF<<<dim3(TOK/128, Dd/16), 256>>>(G.y, G.xTh, G.xTl, Dd, TOK/16);
    gemm_fr<0><<<dim3(TOK/128, Vv/128), 256, SM_FR>>>(G.xTh, G.xTl, G.oWh, G.oWl,
        out_b, out, nullptr, nullptr, Dd, TOK/16, Vv/8, Vv, 0, 0);
    softmax_vocab<<<TOK, 1024>>>(out);
}

// round 15
// speedup vs baseline: 1.0745x; 1.0745x over previous
#include <cuda_runtime.h>
#include <cuda_bf16.h>
#include <math.h>
#include <stdint.h>

#define Bn   4
#define Ss   512
#define Dd   512
#define Hh   8
#define DKk  64
#define Nl   6
#define Vv   32000
#define FFf  2048
#define TOK  (Bn*Ss)

// ---------------- fp32 scratch ----------------
__device__ __align__(16) float g_x[TOK*Dd];
__device__ __align__(16) float g_y[TOK*Dd];
__device__ __align__(16) float g_tmp[TOK*Dd];

// ---------------- packed bf16x2 hi/lo ----------------
#define DD2  (Dd*Dd/2)
__device__ __align__(16) uint32_t g_encW_h[24*DD2], g_encW_l[24*DD2];
__device__ __align__(16) uint32_t g_decSW_h[24*DD2], g_decSW_l[24*DD2];
__device__ __align__(16) uint32_t g_decCW_h[24*DD2], g_decCW_l[24*DD2];
#define W1SZ (Dd*FFf/2)
__device__ __align__(16) uint32_t g_encW1_h[Nl*W1SZ], g_encW1_l[Nl*W1SZ];
__device__ __align__(16) uint32_t g_encW2_h[Nl*W1SZ], g_encW2_l[Nl*W1SZ];
__device__ __align__(16) uint32_t g_decW1_h[Nl*W1SZ], g_decW1_l[Nl*W1SZ];
__device__ __align__(16) uint32_t g_decW2_h[Nl*W1SZ], g_decW2_l[Nl*W1SZ];
#define OWSZ (Dd*Vv/2)
__device__ __align__(16) uint32_t g_outW_h[OWSZ], g_outW_l[OWSZ];
#define KVC  (TOK*Dd/2)
__device__ __align__(16) uint32_t g_xT_h[KVC],  g_xT_l[KVC];        // encoder-chain activation^T
__device__ __align__(16) uint32_t g_yT_h[KVC],  g_yT_l[KVC];        // decoder-chain activation^T
__device__ __align__(16) uint32_t g_qkvP_h[3*KVC], g_qkvP_l[3*KVC]; // q^T | k^T | vP
__device__ __align__(16) uint32_t g_oT_h[KVC],  g_oT_l[KVC];        // attn out^T
__device__ __align__(16) uint32_t g_xeT_h[KVC], g_xeT_l[KVC];       // encoder out^T
__device__ __align__(16) uint32_t g_xKV_h[12*KVC], g_xKV_l[12*KVC]; // cross K^T|V, 6 layers
#define FTSZ ((FFf/2)*TOK)
__device__ __align__(16) uint32_t g_fT_h[FTSZ], g_fT_l[FTSZ];       // ffn hidden^T

// ---------------- helpers ----------------
__device__ __forceinline__ void cvt_pair(float x0, float x1, uint32_t& hi, uint32_t& lo)
{
    uint32_t h;
    asm("cvt.rn.bf16x2.f32 %0, %1, %2;" : "=r"(h) : "f"(x1), "f"(x0));
    __nv_bfloat162 hb = *reinterpret_cast<__nv_bfloat162*>(&h);
    float r0 = x0 - __bfloat162float(hb.x);
    float r1 = x1 - __bfloat162float(hb.y);
    uint32_t l;
    asm("cvt.rn.bf16x2.f32 %0, %1, %2;" : "=r"(l) : "f"(r1), "f"(r0));
    hi = h; lo = l;
}

__device__ __forceinline__ uint32_t mulbf2(uint32_t a, uint32_t b)
{
    uint32_t d; asm("mul.rn.bf16x2 %0,%1,%2;" : "=r"(d) : "r"(a), "r"(b)); return d;
}

__device__ __forceinline__ void mma16816(float* c, const uint32_t* a, const uint32_t* b)
{
    asm volatile(
        "mma.sync.aligned.m16n8k16.row.col.f32.bf16.bf16.f32 "
        "{%0,%1,%2,%3}, {%4,%5,%6,%7}, {%8,%9}, {%0,%1,%2,%3};\n"
        : "+f"(c[0]), "+f"(c[1]), "+f"(c[2]), "+f"(c[3])
        : "r"(a[0]), "r"(a[1]), "r"(a[2]), "r"(a[3]), "r"(b[0]), "r"(b[1]));
}

__device__ __forceinline__ void cp_async16(uint32_t s, const void* g)
{
    asm volatile("cp.async.cg.shared.global [%0], [%1], 16;" :: "r"(s), "l"(g));
}
#define CP_COMMIT() asm volatile("cp.async.commit_group;")

__device__ __forceinline__ void cp_wait_n(int n)
{
    switch (n) {
    case 0: asm volatile("cp.async.wait_group 0;"); break;
    case 1: asm volatile("cp.async.wait_group 1;"); break;
    case 2: asm volatile("cp.async.wait_group 2;"); break;
    default: asm volatile("cp.async.wait_group 3;"); break;
    }
}

// ---------------- conversion kernels ----------------
__global__ __launch_bounds__(256)
void convB(const float* __restrict__ W, uint32_t* __restrict__ H,
           uint32_t* __restrict__ L, int C)
{
    long long kp = blockIdx.y;
    int c = blockIdx.x * 256 + threadIdx.x;
    float a = W[(2*kp) * (long long)C + c];
    float b = W[(2*kp+1) * (long long)C + c];
    uint32_t h, l; cvt_pair(a, b, h, l);
    long long o = kp * C + c;
    H[o] = h; L[o] = l;
}

// ---------------- all-packed mma.sync GEMM (MHA + FFN + vocab) ----------------
// PACKMODE 0: C fp32 row-major
// PACKMODE 1: bf16x2 hi/lo transposed-packed [N/2][ldc]
// PACKMODE 3: per-z: zi < rThresh -> mode 1; else mode 2 (row-pair packed [M/2][ldc2])
template<int TBM, int TBN, int NTHREADS, int WARPS_M, int STAGES, int PACKMODE>
__global__ __launch_bounds__(NTHREADS)
void gemm_ap(const uint32_t* __restrict__ AH, const uint32_t* __restrict__ AL,
             const uint32_t* __restrict__ BH, const uint32_t* __restrict__ BL,
             const float* __restrict__ bias, float* __restrict__ C,
             uint32_t* __restrict__ CH, uint32_t* __restrict__ CL,
             int K, int ldap, int ldbp, int ldc, int ldc2,
             long long sAo, long long sAi, long long sBo, long long sBi,
             long long sCo, long long sCi, int Hsub, int rThresh,
             float alpha, int doBias, int doRelu)
{
    constexpr int WARPS   = NTHREADS / 32;
    constexpr int WARPS_N = WARPS / WARPS_M;
    constexpr int WM = TBM / WARPS_M;
    constexpr int WN = TBN / WARPS_N;
    constexpr int MT = WM / 16;
    constexpr int NT = WN / 8;
    constexpr int AS = TBM + 8;
    constexpr int BS = TBN + 8;
    constexpr int ASZ = 16 * AS;
    constexpr int BSZ = 16 * BS;
    constexpr int AC = (16 * (TBM / 4)) / NTHREADS;
    constexpr int BC = (16 * (TBN / 4)) / NTHREADS;

    extern __shared__ uint32_t smem[];
    uint32_t* sAh = smem;
    uint32_t* sAl = smem + STAGES * ASZ;
    uint32_t* sBh = smem + 2 * STAGES * ASZ;
    uint32_t* sBl = smem + 2 * STAGES * ASZ + STAGES * BSZ;

    int z = blockIdx.z;
    int zo = z / Hsub, zi = z % Hsub;
    const uint32_t* Ahb = AH + zo * sAo + zi * sAi;
    const uint32_t* Alb = AL + zo * sAo + zi * sAi;
    const uint32_t* Bhb = BH + zo * sBo + zi * sBi;
    const uint32_t* Blb = BL + zo * sBo + zi * sBi;
    float*    Cb  = (PACKMODE == 0) ? (C + zo * sCo + zi * sCi) : nullptr;
    uint32_t* CHb = (PACKMODE != 0) ? (CH + zo * sCo + zi * sCi) : nullptr;
    uint32_t* CLb = (PACKMODE != 0) ? (CL + zo * sCo + zi * sCi) : nullptr;

    int tid = threadIdx.x;
    int wid = tid >> 5, lane = tid & 31;
    int wm = wid % WARPS_M, wn = wid / WARPS_M;
    int group = lane >> 2, tig = lane & 3;
    int row0 = blockIdx.x * TBM;
    int col0 = blockIdx.y * TBN;

    auto cpStage = [&](int k0, int st) {
        int kp0 = k0 >> 1;
        uint32_t ah0 = (uint32_t)__cvta_generic_to_shared(sAh + st * ASZ);
        uint32_t al0 = (uint32_t)__cvta_generic_to_shared(sAl + st * ASZ);
#pragma unroll
        for (int j = 0; j < AC; j++) {
            int ci = tid + j * NTHREADS;
            int rr = ci / (TBM / 4), cc = ci % (TBM / 4);
            long long go = (long long)(kp0 + rr) * ldap + row0 + cc * 4;
            uint32_t so = (rr * AS + cc * 4) * 4;
            cp_async16(ah0 + so, Ahb + go);
            cp_async16(al0 + so, Alb + go);
        }
        uint32_t bh0 = (uint32_t)__cvta_generic_to_shared(sBh + st * BSZ);
        uint32_t bl0 = (uint32_t)__cvta_generic_to_shared(sBl + st * BSZ);
#pragma unroll
        for (int j = 0; j < BC; j++) {
            int ci = tid + j * NTHREADS;
            int rr = ci / (TBN / 4), cc = ci % (TBN / 4);
            long long go = (long long)(kp0 + rr) * ldbp + col0 + cc * 4;
            uint32_t so = (rr * BS + cc * 4) * 4;
            cp_async16(bh0 + so, Bhb + go);
            cp_async16(bl0 + so, Blb + go);
        }
        CP_COMMIT();
    };

    float acc[MT][NT][4];
#pragma unroll
    for (int i = 0; i < MT; i++)
#pragma unroll
        for (int j = 0; j < NT; j++)
#pragma unroll
            for (int t = 0; t < 4; t++) acc[i][j][t] = 0.f;

    int kpref = 0;
#pragma unroll
    for (int s = 0; s < STAGES - 1; s++) { cpStage(kpref, s); kpref += 32; }

    int st = 0;
    for (int k0 = 0; k0 < K; k0 += 32) {
        if (kpref < K) {
            cpStage(kpref, (kpref >> 5) % STAGES);
            kpref += 32;
        }
        cp_wait_n(((kpref - k0) >> 5) - 1);
        __syncthreads();

        const uint32_t* Ahs = sAh + st * ASZ;
        const uint32_t* Als = sAl + st * ASZ;
        const uint32_t* Bhs = sBh + st * BSZ;
        const uint32_t* Bls = sBl + st * BSZ;
#pragma unroll
        for (int ks = 0; ks < 2; ks++) {
            uint32_t ah[MT][4], al[MT][4], bh[NT][2], bl[NT][2];
            int kp0 = ks * 8 + tig, kp1 = kp0 + 4;
#pragma unroll
            for (int mt = 0; mt < MT; mt++) {
                int r = wm * WM + mt * 16 + group;
                ah[mt][0] = Ahs[kp0 * AS + r];     al[mt][0] = Als[kp0 * AS + r];
                ah[mt][1] = Ahs[kp0 * AS + r + 8]; al[mt][1] = Als[kp0 * AS + r + 8];
                ah[mt][2] = Ahs[kp1 * AS + r];     al[mt][2] = Als[kp1 * AS + r];
                ah[mt][3] = Ahs[kp1 * AS + r + 8]; al[mt][3] = Als[kp1 * AS + r + 8];
            }
#pragma unroll
            for (int nt = 0; nt < NT; nt++) {
                int c = wn * WN + nt * 8 + group;
                bh[nt][0] = Bhs[kp0 * BS + c];  bl[nt][0] = Bls[kp0 * BS + c];
                bh[nt][1] = Bhs[kp1 * BS + c];  bl[nt][1] = Bls[kp1 * BS + c];
            }
#pragma unroll
            for (int mt = 0; mt < MT; mt++)
#pragma unroll
                for (int nt = 0; nt < NT; nt++)
                    mma16816(acc[mt][nt], ah[mt], bh[nt]);
#pragma unroll
            for (int mt = 0; mt < MT; mt++)
#pragma unroll
                for (int nt = 0; nt < NT; nt++)
                    mma16816(acc[mt][nt], al[mt], bh[nt]);
#pragma unroll
            for (int mt = 0; mt < MT; mt++)
#pragma unroll
                for (int nt = 0; nt < NT; nt++)
                    mma16816(acc[mt][nt], ah[mt], bl[nt]);
        }
        __syncthreads();
        if (++st == STAGES) st = 0;
    }

    int effMode = (PACKMODE == 3) ? ((zi >= rThresh) ? 2 : 1) : PACKMODE;

#pragma unroll
    for (int mt = 0; mt < MT; mt++) {
        int r = row0 + wm * WM + mt * 16 + group;
#pragma unroll
        for (int nt = 0; nt < NT; nt++) {
            int c = col0 + wn * WN + nt * 8 + tig * 2;
            float v00 = acc[mt][nt][0] * alpha;
            float v01 = acc[mt][nt][1] * alpha;
            float v10 = acc[mt][nt][2] * alpha;
            float v11 = acc[mt][nt][3] * alpha;
            if (doBias) {
                float2 bb = *reinterpret_cast<const float2*>(&bias[c]);
                v00 += bb.x; v01 += bb.y; v10 += bb.x; v11 += bb.y;
            }
            if (doRelu) {
                v00 = fmaxf(v00, 0.f); v01 = fmaxf(v01, 0.f);
                v10 = fmaxf(v10, 0.f); v11 = fmaxf(v11, 0.f);
            }
            if (PACKMODE == 0) {
                *reinterpret_cast<float2*>(&Cb[(long long)r * ldc + c])       = make_float2(v00, v01);
                *reinterpret_cast<float2*>(&Cb[(long long)(r + 8) * ldc + c]) = make_float2(v10, v11);
            } else if (effMode == 1) {
                long long base = (long long)(c >> 1) * ldc + r;
                uint32_t h, l;
                cvt_pair(v00, v01, h, l); CHb[base] = h;     CLb[base] = l;
                cvt_pair(v10, v11, h, l); CHb[base + 8] = h; CLb[base + 8] = l;
            } else {
                float u00 = __shfl_down_sync(0xffffffffu, v00, 4);
                float u01 = __shfl_down_sync(0xffffffffu, v01, 4);
                float u10 = __shfl_down_sync(0xffffffffu, v10, 4);
                float u11 = __shfl_down_sync(0xffffffffu, v11, 4);
                if (!(group & 1)) {
                    long long b0 = (long long)(r >> 1) * ldc2 + c;
                    long long b8 = (long long)((r + 8) >> 1) * ldc2 + c;
                    uint32_t h, l;
                    cvt_pair(v00, u00, h, l); CHb[b0]     = h; CLb[b0]     = l;
                    cvt_pair(v01, u01, h, l); CHb[b0 + 1] = h; CLb[b0 + 1] = l;
                    cvt_pair(v10, u10, h, l); CHb[b8]     = h; CLb[b8]     = l;
                    cvt_pair(v11, u11, h, l); CHb[b8 + 1] = h; CLb[b8 + 1] = l;
                }
            }
        }
    }
}

// ---------------- fused flash attention ----------------
#define FA_STRIDE 68
#define FA_TSZ (32 * FA_STRIDE)
__global__ __launch_bounds__(128)
void flash_attn(const uint32_t* __restrict__ Qh, const uint32_t* __restrict__ Ql,
                const uint32_t* __restrict__ Kh, const uint32_t* __restrict__ Kl,
                const uint32_t* __restrict__ Vh, const uint32_t* __restrict__ Vl,
                uint32_t* __restrict__ Oh, uint32_t* __restrict__ Ol, int causal)
{
    extern __shared__ uint32_t smem[];
    uint32_t* sKh = smem;
    uint32_t* sKl = smem + 2 * FA_TSZ;
    uint32_t* sVh = smem + 4 * FA_TSZ;
    uint32_t* sVl = smem + 6 * FA_TSZ;

    int qb = blockIdx.x;
    int b  = blockIdx.y / Hh;
    int h  = blockIdx.y % Hh;
    int tid = threadIdx.x;
    int wid = tid >> 5, lane = tid & 31;
    int group = lane >> 2, tig = lane & 3;
    int tokBase = b * Ss + qb * 64 + wid * 16;

    uint32_t qh[4][4], ql[4][4];
    const uint32_t SC = 0x3E003E00u;
#pragma unroll
    for (int ks = 0; ks < 4; ks++) {
        int kpa = h * 32 + ks * 8 + tig;
        long long b0 = (long long)kpa * TOK + tokBase + group;
        long long b2 = (long long)(kpa + 4) * TOK + tokBase + group;
        qh[ks][0] = mulbf2(Qh[b0], SC);     ql[ks][0] = mulbf2(Ql[b0], SC);
        qh[ks][1] = mulbf2(Qh[b0 + 8], SC); ql[ks][1] = mulbf2(Ql[b0 + 8], SC);
        qh[ks][2] = mulbf2(Qh[b2], SC);     ql[ks][2] = mulbf2(Ql[b2], SC);
        qh[ks][3] = mulbf2(Qh[b2 + 8], SC); ql[ks][3] = mulbf2(Ql[b2 + 8], SC);
    }

    float m0 = -INFINITY, m1 = -INFINITY, l0 = 0.f, l1 = 0.f;
    float acc_o[8][4];
#pragma unroll
    for (int nt = 0; nt < 8; nt++)
#pragma unroll
        for (int t = 0; t < 4; t++) acc_o[nt][t] = 0.f;

    int nkb = causal ? (qb + 1) : (Ss / 64);

    auto cpStage = [&](int kb, int stg) {
        uint32_t kh0 = (uint32_t)__cvta_generic_to_shared(sKh + stg * FA_TSZ);
        uint32_t kl0 = (uint32_t)__cvta_generic_to_shared(sKl + stg * FA_TSZ);
        uint32_t vh0 = (uint32_t)__cvta_generic_to_shared(sVh + stg * FA_TSZ);
        uint32_t vl0 = (uint32_t)__cvta_generic_to_shared(sVl + stg * FA_TSZ);
#pragma unroll
        for (int i = 0; i < 4; i++) {
            int idx = tid + i * 128;
            int row = idx >> 4, c4 = idx & 15;
            uint32_t so = (row * FA_STRIDE + c4 * 4) * 4;
            long long gK = (long long)(h * 32 + row) * TOK + b * Ss + kb * 64 + c4 * 4;
            cp_async16(kh0 + so, Kh + gK);
            cp_async16(kl0 + so, Kl + gK);
            long long gV = (long long)(b * (Ss / 2) + kb * 32 + row) * Dd + h * 64 + c4 * 4;
            cp_async16(vh0 + so, Vh + gV);
            cp_async16(vl0 + so, Vl + gV);
        }
        CP_COMMIT();
    };

    cpStage(0, 0);
    for (int kb = 0; kb < nkb; kb++) {
        if (kb + 1 < nkb) {
            cpStage(kb + 1, (kb + 1) & 1);
            asm volatile("cp.async.wait_group 1;");
        } else {
            asm volatile("cp.async.wait_group 0;");
        }
        __syncthreads();
        int stg = kb & 1;
        const uint32_t* Ksh = sKh + stg * FA_TSZ;
        const uint32_t* Ksl = sKl + stg * FA_TSZ;
        const uint32_t* Vsh = sVh + stg * FA_TSZ;
        const uint32_t* Vsl = sVl + stg * FA_TSZ;

        float s[8][4];
#pragma unroll
        for (int nt = 0; nt < 8; nt++)
#pragma unroll
            for (int t = 0; t < 4; t++) s[nt][t] = 0.f;
#pragma unroll
        for (int ks = 0; ks < 4; ks++) {
            int r0 = (ks * 8 + tig) * FA_STRIDE, r1 = r0 + 4 * FA_STRIDE;
            uint32_t bhf[8][2], blf[8][2];
#pragma unroll
            for (int nt = 0; nt < 8; nt++) {
                int c = nt * 8 + group;
                bhf[nt][0] = Ksh[r0 + c]; bhf[nt][1] = Ksh[r1 + c];
                blf[nt][0] = Ksl[r0 + c]; blf[nt][1] = Ksl[r1 + c];
            }
#pragma unroll
            for (int nt = 0; nt < 8; nt++) mma16816(s[nt], qh[ks], bhf[nt]);
#pragma unroll
            for (int nt = 0; nt < 8; nt++) mma16816(s[nt], ql[ks], bhf[nt]);
#pragma unroll
            for (int nt = 0; nt < 8; nt++) mma16816(s[nt], qh[ks], blf[nt]);
        }

        if (causal && kb == qb) {
            int r0 = wid * 16 + group, r1 = r0 + 8;
#pragma unroll
            for (int nt = 0; nt < 8; nt++) {
                int c0 = nt * 8 + tig * 2;
                if (c0     > r0) s[nt][0] = -1e9f;
                if (c0 + 1 > r0) s[nt][1] = -1e9f;
                if (c0     > r1) s[nt][2] = -1e9f;
                if (c0 + 1 > r1) s[nt][3] = -1e9f;
            }
        }

        float bm0 = -INFINITY, bm1 = -INFINITY;
#pragma unroll
        for (int nt = 0; nt < 8; nt++) {
            bm0 = fmaxf(bm0, fmaxf(s[nt][0], s[nt][1]));
            bm1 = fmaxf(bm1, fmaxf(s[nt][2], s[nt][3]));
        }
        bm0 = fmaxf(bm0, __shfl_xor_sync(0xffffffffu, bm0, 1));
        bm0 = fmaxf(bm0, __shfl_xor_sync(0xffffffffu, bm0, 2));
        bm1 = fmaxf(bm1, __shfl_xor_sync(0xffffffffu, bm1, 1));
        bm1 = fmaxf(bm1, __shfl_xor_sync(0xffffffffu, bm1, 2));
        float nm0 = fmaxf(m0, bm0), nm1 = fmaxf(m1, bm1);
        float a0f = __expf(m0 - nm0), a1f = __expf(m1 - nm1);
        m0 = nm0; m1 = nm1;
        float rs0 = 0.f, rs1 = 0.f;
#pragma unroll
        for (int nt = 0; nt < 8; nt++) {
            s[nt][0] = __expf(s[nt][0] - nm0);
            s[nt][1] = __expf(s[nt][1] - nm0);
            s[nt][2] = __expf(s[nt][2] - nm1);
            s[nt][3] = __expf(s[nt][3] - nm1);
            rs0 += s[nt][0] + s[nt][1];
            rs1 += s[nt][2] + s[nt][3];
        }
        rs0 += __shfl_xor_sync(0xffffffffu, rs0, 1);
        rs0 += __shfl_xor_sync(0xffffffffu, rs0, 2);
        rs1 += __shfl_xor_sync(0xffffffffu, rs1, 1);
        rs1 += __shfl_xor_sync(0xffffffffu, rs1, 2);
        l0 = l0 * a0f + rs0;
        l1 = l1 * a1f + rs1;
#pragma unroll
        for (int nt = 0; nt < 8; nt++) {
            acc_o[nt][0] *= a0f; acc_o[nt][1] *= a0f;
            acc_o[nt][2] *= a1f; acc_o[nt][3] *= a1f;
        }

        uint32_t ph[4][4], pl[4][4];
#pragma unroll
        for (int j = 0; j < 4; j++) {
            cvt_pair(s[2*j  ][0], s[2*j  ][1], ph[j][0], pl[j][0]);
            cvt_pair(s[2*j  ][2], s[2*j  ][3], ph[j][1], pl[j][1]);
            cvt_pair(s[2*j+1][0], s[2*j+1][1], ph[j][2], pl[j][2]);
            cvt_pair(s[2*j+1][2], s[2*j+1][3], ph[j][3], pl[j][3]);
        }

#pragma unroll
        for (int j = 0; j < 4; j++) {
            int r0 = (j * 8 + tig) * FA_STRIDE, r1 = r0 + 4 * FA_STRIDE;
            uint32_t vbh[8][2], vbl[8][2];
#pragma unroll
            for (int nt = 0; nt < 8; nt++) {
                int c = nt * 8 + group;
                vbh[nt][0] = Vsh[r0 + c]; vbh[nt][1] = Vsh[r1 + c];
                vbl[nt][0] = Vsl[r0 + c]; vbl[nt][1] = Vsl[r1 + c];
            }
#pragma unroll
            for (int nt = 0; nt < 8; nt++) mma16816(acc_o[nt], ph[j], vbh[nt]);
#pragma unroll
            for (int nt = 0; nt < 8; nt++) mma16816(acc_o[nt], pl[j], vbh[nt]);
#pragma unroll
            for (int nt = 0; nt < 8; nt++) mma16816(acc_o[nt], ph[j], vbl[nt]);
        }
        __syncthreads();
    }

    float inv0 = 1.0f / l0, inv1 = 1.0f / l1;
#pragma unroll
    for (int nt = 0; nt < 8; nt++) {
        int cp = h * 32 + nt * 4 + tig;
        long long bo = (long long)cp * TOK + tokBase + group;
        uint32_t hh, ll;
        cvt_pair(acc_o[nt][0] * inv0, acc_o[nt][1] * inv0, hh, ll);
        Oh[bo] = hh; Ol[bo] = ll;
        cvt_pair(acc_o[nt][2] * inv1, acc_o[nt][3] * inv1, hh, ll);
        Oh[bo + 8] = hh; Ol[bo + 8] = ll;
    }
}

// ---------------- vocab softmax ----------
__global__ __launch_bounds__(1024)
void softmax_vocab(float* __restrict__ P)
{
    float* p = P + (long long)blockIdx.x * Vv;
    int t = threadIdx.x;
    __shared__ float red[32];
    float v[32];
    float mx = -3.0e38f;
#pragma unroll
    for (int i = 0; i < 32; i++) {
        int idx = t + i * 1024;
        v[i] = (idx < Vv) ? p[idx] : -3.0e38f;
        mx = fmaxf(mx, v[i]);
    }
    for (int o = 16; o; o >>= 1) mx = fmaxf(mx, __shfl_xor_sync(0xffffffffu, mx, o));
    if ((t & 31) == 0) red[t >> 5] = mx;
    __syncthreads();
    if (t < 32) {
        float m2 = red[t];
        for (int o = 16; o; o >>= 1) m2 = fmaxf(m2, __shfl_xor_sync(0xffffffffu, m2, o));
        if (t == 0) red[0] = m2;
    }
    __syncthreads();
    mx = red[0];
    __syncthreads();
    float sum = 0.f;
#pragma unroll
    for (int i = 0; i < 32; i++) { v[i] = __expf(v[i] - mx); sum += v[i]; }
    for (int o = 16; o; o >>= 1) sum += __shfl_xor_sync(0xffffffffu, sum, o);
    if ((t & 31) == 0) red[t >> 5] = sum;
    __syncthreads();
    if (t < 32) {
        float s2 = red[t];
        for (int o = 16; o; o >>= 1) s2 += __shfl_xor_sync(0xffffffffu, s2, o);
        if (t == 0) red[0] = s2;
    }
    __syncthreads();
    float inv = 1.0f / red[0];
#pragma unroll
    for (int i = 0; i < 32; i++) {
        int idx = t + i * 1024;
        if (idx < Vv) p[idx] = v[i] * inv;
    }
}

// ---------------- fused add + LayerNorm + transposed pack ----------
// x = LN(x + sub) in place; also writes bf16x2 hi/lo transposed-packed [Dd/2][TOK]
__global__ __launch_bounds__(256)
void add_ln_pack(float* __restrict__ x, const float* __restrict__ sub,
                 uint32_t* __restrict__ H, uint32_t* __restrict__ L)
{
    int row = blockIdx.x;
    float* xr = x + (long long)row * Dd;
    const float* sr = sub + (long long)row * Dd;
    int t = threadIdx.x;
    __shared__ float red[256];

    float v0 = xr[t] + sr[t];
    float v1 = xr[t + 256] + sr[t + 256];
    red[t] = v0 + v1; __syncthreads();
    for (int o = 128; o; o >>= 1) { if (t < o) red[t] += red[t + o]; __syncthreads(); }
    float mu = red[0] * (1.0f / 512.0f); __syncthreads();
    float d0 = v0 - mu, d1 = v1 - mu;
    red[t] = d0 * d0 + d1 * d1; __syncthreads();
    for (int o = 128; o; o >>= 1) { if (t < o) red[t] += red[t + o]; __syncthreads(); }
    float inv = rsqrtf(red[0] * (1.0f / 512.0f) + 1e-5f);
    float n0 = d0 * inv, n1 = d1 * inv;
    xr[t] = n0;
    xr[t + 256] = n1;

    // pack: features (2kp, 2kp+1) -> [kp][row]
    float p0 = __shfl_down_sync(0xffffffffu, n0, 1);
    float p1 = __shfl_down_sync(0xffffffffu, n1, 1);
    if (!(t & 1)) {
        uint32_t h, l;
        long long o0 = (long long)(t >> 1) * TOK + row;
        cvt_pair(n0, p0, h, l); H[o0] = h; L[o0] = l;
        long long o1 = (long long)((t + 256) >> 1) * TOK + row;
        cvt_pair(n1, p1, h, l); H[o1] = h; L[o1] = l;
    }
}

// ---------------- embedding + PE + transposed pack ----------
__global__ __launch_bounds__(512)
void embed_pe_pack(const int* __restrict__ tok, const float* __restrict__ emb,
                   float* __restrict__ out,
                   uint32_t* __restrict__ H, uint32_t* __restrict__ L)
{
    int idx = blockIdx.x;
    int s = idx % Ss;
    int j = threadIdx.x;
    int tk = tok[idx];
    float ang = (float)s * powf(10000.0f, -2.0f * (float)j / 512.0f);
    float pe = (j & 1) ? cosf(ang) : sinf(ang);
    float v = emb[(long long)tk * Dd + j] + pe;
    out[(long long)idx * Dd + j] = v;

    float p = __shfl_down_sync(0xffffffffu, v, 1);
    if (!(j & 1)) {
        uint32_t h, l;
        cvt_pair(v, p, h, l);
        long long o = (long long)(j >> 1) * TOK + idx;
        H[o] = h; L[o] = l;
    }
}

// ---------------- host ----------------
static const int SM_AP64_3  = (4 * 3 * 16 * (64 + 8)) * 4;     // 55,296
static const int SM_AP128_3 = (4 * 3 * 16 * (128 + 8)) * 4;    // 104,448
static const int SM_FA      = 8 * FA_TSZ * 4;                  // 69,632

struct GPtrs {
    float *x, *y, *tmp;
    uint32_t *encWh, *encWl, *decSWh, *decSWl, *decCWh, *decCWl;
    uint32_t *eW1h, *eW1l, *eW2h, *eW2l, *dW1h, *dW1l, *dW2h, *dW2l;
    uint32_t *oWh, *oWl;
    uint32_t *xTh, *xTl, *yTh, *yTl, *qkvPh, *qkvPl, *oTh, *oTl;
    uint32_t *xeTh, *xeTl, *xKVh, *xKVl, *fTh, *fTl;
};

// self-attention: input already packed (aTh/aTl)
static void run_mha_self(GPtrs& G, const uint32_t* aTh, const uint32_t* aTl,
                         const uint32_t* wh, const uint32_t* wl, float* out, bool causal)
{
    {
        dim3 g(TOK/64, Dd/64, 3);
        gemm_ap<64,64,128,2,3,3><<<g, 128, SM_AP64_3>>>(aTh, aTl, wh, wl,
            nullptr, nullptr, G.qkvPh, G.qkvPl,
            Dd, TOK, Dd, TOK, Dd,
            0, 0, 0, DD2, 0, KVC, 3, 2, 1.0f, 0, 0);
    }
    flash_attn<<<dim3(Ss/64, Bn*Hh), 128, SM_FA>>>(
        G.qkvPh, G.qkvPl, G.qkvPh + KVC, G.qkvPl + KVC,
        G.qkvPh + 2*KVC, G.qkvPl + 2*KVC, G.oTh, G.oTl, causal ? 1 : 0);
    {
        dim3 g(TOK/64, Dd/64, 1);
        gemm_ap<64,64,128,2,3,0><<<g, 128, SM_AP64_3>>>(G.oTh, G.oTl, wh + 3*DD2, wl + 3*DD2,
            nullptr, out, nullptr, nullptr,
            Dd, TOK, Dd, Dd, Dd,
            0, 0, 0, 0, 0, 0, 1, 0, 1.0f, 0, 0);
    }
}

static void run_mha_cross(GPtrs& G, const uint32_t* aTh, const uint32_t* aTl, int layer,
                          const uint32_t* wh, const uint32_t* wl, float* out)
{
    {
        dim3 g(TOK/64, Dd/64, 1);
        gemm_ap<64,64,128,2,3,1><<<g, 128, SM_AP64_3>>>(aTh, aTl, wh, wl,
            nullptr, nullptr, G.qkvPh, G.qkvPl,
            Dd, TOK, Dd, TOK, Dd,
            0, 0, 0, 0, 0, 0, 1, 0, 1.0f, 0, 0);
    }
    const uint32_t* kh = G.xKVh + (long long)layer * 2 * KVC;
    const uint32_t* kl = G.xKVl + (long long)layer * 2 * KVC;
    flash_attn<<<dim3(Ss/64, Bn*Hh), 128, SM_FA>>>(
        G.qkvPh, G.qkvPl, kh, kl, kh + KVC, kl + KVC, G.oTh, G.oTl, 0);
    {
        dim3 g(TOK/64, Dd/64, 1);
        gemm_ap<64,64,128,2,3,0><<<g, 128, SM_AP64_3>>>(G.oTh, G.oTl, wh + 3*DD2, wl + 3*DD2,
            nullptr, out, nullptr, nullptr,
            Dd, TOK, Dd, Dd, Dd,
            0, 0, 0, 0, 0, 0, 1, 0, 1.0f, 0, 0);
    }
}

static void run_ffn(GPtrs& G, const uint32_t* aTh, const uint32_t* aTl,
                    const uint32_t* w1h, const uint32_t* w1l, const float* b1,
                    const uint32_t* w2h, const uint32_t* w2l, const float* b2)
{
    {
        dim3 g(TOK/128, FFf/128, 1);
        gemm_ap<128,128,256,4,3,1><<<g, 256, SM_AP128_3>>>(aTh, aTl, w1h, w1l,
            b1, nullptr, G.fTh, G.fTl,
            Dd, TOK, FFf, TOK, Dd,
            0, 0, 0, 0, 0, 0, 1, 0, 1.0f, 1, 1);
    }
    {
        dim3 g(TOK/64, Dd/64, 1);
        gemm_ap<64,64,128,2,3,0><<<g, 128, SM_AP64_3>>>(G.fTh, G.fTl, w2h, w2l,
            b2, G.tmp, nullptr, nullptr,
            FFf, TOK, Dd, Dd, Dd,
            0, 0, 0, 0, 0, 0, 1, 0, 1.0f, 1, 0);
    }
}

extern "C" void kernel_launch(void* const* d_in, const int* in_sizes, int n_in,
                              void* d_out, int out_size)
{
    const int*   src           = (const int*)  d_in[0];
    const int*   trg           = (const int*)  d_in[1];
    const float* src_emb       = (const float*)d_in[2];
    const float* trg_emb       = (const float*)d_in[3];
    const float* enc_qkvo      = (const float*)d_in[4];
    const float* enc_ffn_w1    = (const float*)d_in[5];
    const float* enc_ffn_b1    = (const float*)d_in[6];
    const float* enc_ffn_w2    = (const float*)d_in[7];
    const float* enc_ffn_b2    = (const float*)d_in[8];
    const float* dec_self_qkvo = (const float*)d_in[9];
    const float* dec_cross_qkvo= (const float*)d_in[10];
    const float* dec_ffn_w1    = (const float*)d_in[11];
    const float* dec_ffn_b1    = (const float*)d_in[12];
    const float* dec_ffn_w2    = (const float*)d_in[13];
    const float* dec_ffn_b2    = (const float*)d_in[14];
    const float* out_w         = (const float*)d_in[15];
    const float* out_b         = (const float*)d_in[16];
    float* out = (float*)d_out;

    cudaFuncSetAttribute(gemm_ap<64,64,128,2,3,0>,
                         cudaFuncAttributeMaxDynamicSharedMemorySize, SM_AP64_3);
    cudaFuncSetAttribute(gemm_ap<64,64,128,2,3,1>,
                         cudaFuncAttributeMaxDynamicSharedMemorySize, SM_AP64_3);
    cudaFuncSetAttribute(gemm_ap<64,64,128,2,3,3>,
                         cudaFuncAttributeMaxDynamicSharedMemorySize, SM_AP64_3);
    cudaFuncSetAttribute(gemm_ap<128,128,256,4,3,0>,
                         cudaFuncAttributeMaxDynamicSharedMemorySize, SM_AP128_3);
    cudaFuncSetAttribute(gemm_ap<128,128,256,4,3,1>,
                         cudaFuncAttributeMaxDynamicSharedMemorySize, SM_AP128_3);
    cudaFuncSetAttribute(flash_attn,
                         cudaFuncAttributeMaxDynamicSharedMemorySize, SM_FA);

    GPtrs G;
    cudaGetSymbolAddress((void**)&G.x,    g_x);
    cudaGetSymbolAddress((void**)&G.y,    g_y);
    cudaGetSymbolAddress((void**)&G.tmp,  g_tmp);
    cudaGetSymbolAddress((void**)&G.encWh,  g_encW_h);  cudaGetSymbolAddress((void**)&G.encWl, g_encW_l);
    cudaGetSymbolAddress((void**)&G.decSWh, g_decSW_h); cudaGetSymbolAddress((void**)&G.decSWl, g_decSW_l);
    cudaGetSymbolAddress((void**)&G.decCWh, g_decCW_h); cudaGetSymbolAddress((void**)&G.decCWl, g_decCW_l);
    cudaGetSymbolAddress((void**)&G.eW1h,   g_encW1_h); cudaGetSymbolAddress((void**)&G.eW1l, g_encW1_l);
    cudaGetSymbolAddress((void**)&G.eW2h,   g_encW2_h); cudaGetSymbolAddress((void**)&G.eW2l, g_encW2_l);
    cudaGetSymbolAddress((void**)&G.dW1h,   g_decW1_h); cudaGetSymbolAddress((void**)&G.dW1l, g_decW1_l);
    cudaGetSymbolAddress((void**)&G.dW2h,   g_decW2_h); cudaGetSymbolAddress((void**)&G.dW2l, g_decW2_l);
    cudaGetSymbolAddress((void**)&G.oWh,    g_outW_h);  cudaGetSymbolAddress((void**)&G.oWl, g_outW_l);
    cudaGetSymbolAddress((void**)&G.xTh,    g_xT_h);    cudaGetSymbolAddress((void**)&G.xTl, g_xT_l);
    cudaGetSymbolAddress((void**)&G.yTh,    g_yT_h);    cudaGetSymbolAddress((void**)&G.yTl, g_yT_l);
    cudaGetSymbolAddress((void**)&G.qkvPh,  g_qkvP_h);  cudaGetSymbolAddress((void**)&G.qkvPl, g_qkvP_l);
    cudaGetSymbolAddress((void**)&G.oTh,    g_oT_h);    cudaGetSymbolAddress((void**)&G.oTl, g_oT_l);
    cudaGetSymbolAddress((void**)&G.xeTh,   g_xeT_h);   cudaGetSymbolAddress((void**)&G.xeTl, g_xeT_l);
    cudaGetSymbolAddress((void**)&G.xKVh,   g_xKV_h);   cudaGetSymbolAddress((void**)&G.xKVl, g_xKV_l);
    cudaGetSymbolAddress((void**)&G.fTh,    g_fT_h);    cudaGetSymbolAddress((void**)&G.fTl, g_fT_l);

    // weight conversions (once per call)
    convB<<<dim3(Dd / 256,  24 * Dd / 2), 256>>>(enc_qkvo,       G.encWh, G.encWl, Dd);
    convB<<<dim3(Dd / 256,  24 * Dd / 2), 256>>>(dec_self_qkvo,  G.decSWh, G.decSWl, Dd);
    convB<<<dim3(Dd / 256,  24 * Dd / 2), 256>>>(dec_cross_qkvo, G.decCWh, G.decCWl, Dd);
    convB<<<dim3(FFf / 256, Nl * Dd / 2), 256>>>(enc_ffn_w1, G.eW1h, G.eW1l, FFf);
    convB<<<dim3(Dd / 256,  Nl * FFf / 2), 256>>>(enc_ffn_w2, G.eW2h, G.eW2l, Dd);
    convB<<<dim3(FFf / 256, Nl * Dd / 2), 256>>>(dec_ffn_w1, G.dW1h, G.dW1l, FFf);
    convB<<<dim3(Dd / 256,  Nl * FFf / 2), 256>>>(dec_ffn_w2, G.dW2h, G.dW2l, Dd);
    convB<<<dim3(Vv / 256,  Dd / 2), 256>>>(out_w, G.oWh, G.oWl, Vv);

    embed_pe_pack<<<TOK, 512>>>(src, src_emb, G.x, G.xTh, G.xTl);
    embed_pe_pack<<<TOK, 512>>>(trg, trg_emb, G.y, G.yTh, G.yTl);

    // ---------------- Encoder ----------------
    for (int i = 0; i < Nl; i++) {
        run_mha_self(G, G.xTh, G.xTl,
                G.encWh + (long long)i * 4 * DD2, G.encWl + (long long)i * 4 * DD2,
                G.tmp, false);
        add_ln_pack<<<TOK, 256>>>(G.x, G.tmp, G.xTh, G.xTl);
        run_ffn(G, G.xTh, G.xTl,
                G.eW1h + (long long)i * W1SZ, G.eW1l + (long long)i * W1SZ,
                enc_ffn_b1 + (long long)i * FFf,
                G.eW2h + (long long)i * W1SZ, G.eW2l + (long long)i * W1SZ,
                enc_ffn_b2 + (long long)i * Dd);
        if (i == Nl - 1)
            add_ln_pack<<<TOK, 256>>>(G.x, G.tmp, G.xeTh, G.xeTl);
        else
            add_ln_pack<<<TOK, 256>>>(G.x, G.tmp, G.xTh, G.xTl);
    }

    // precompute ALL cross-attn K,V (6 layers) from packed encoder output
    {
        dim3 g(TOK/64, Dd/64, 2 * Nl);
        gemm_ap<64,64,128,2,3,3><<<g, 128, SM_AP64_3>>>(G.xeTh, G.xeTl,
            G.decCWh + DD2, G.decCWl + DD2,
            nullptr, nullptr, G.xKVh, G.xKVl,
            Dd, TOK, Dd, TOK, Dd,
            0, 0, (long long)4 * DD2, DD2, (long long)2 * KVC, KVC,
            2, 1, 1.0f, 0, 0);
    }

    // ---------------- Decoder ----------------
    for (int i = 0; i < Nl; i++) {
        run_mha_self(G, G.yTh, G.yTl,
                G.decSWh + (long long)i * 4 * DD2, G.decSWl + (long long)i * 4 * DD2,
                G.tmp, true);
        add_ln_pack<<<TOK, 256>>>(G.y, G.tmp, G.yTh, G.yTl);

        run_mha_cross(G, G.yTh, G.yTl, i,
                G.decCWh + (long long)i * 4 * DD2, G.decCWl + (long long)i * 4 * DD2,
                G.tmp);
        add_ln_pack<<<TOK, 256>>>(G.y, G.tmp, G.yTh, G.yTl);

        run_ffn(G, G.yTh, G.yTl,
                G.dW1h + (long long)i * W1SZ, G.dW1l + (long long)i * W1SZ,
                dec_ffn_b1 + (long long)i * FFf,
                G.dW2h + (long long)i * W1SZ, G.dW2l + (long long)i * W1SZ,
                dec_ffn_b2 + (long long)i * Dd);
        add_ln_pack<<<TOK, 256>>>(G.y, G.tmp, G.yTh, G.yTl);
    }

    // ---------------- Output projection + vocab softmax ----------------
    {
        dim3 g(TOK/128, Vv/128, 1);
        gemm_ap<128,128,256,4,3,0><<<g, 256, SM_AP128_3>>>(G.yTh, G.yTl, G.oWh, G.oWl,
            out_b, out, nullptr, nullptr,
            Dd, TOK, Vv, Vv, Dd,
            0, 0, 0, 0, 0, 0, 1, 0, 1.0f, 1, 0);
    }
    softmax_vocab<<<TOK, 1024>>>(out);
}

// round 16
// speedup vs baseline: 1.1422x; 1.0630x over previous
#include <cuda_runtime.h>
#include <cuda_bf16.h>
#include <math.h>
#include <stdint.h>

#define Bn   4
#define Ss   512
#define Dd   512
#define Hh   8
#define DKk  64
#define Nl   6
#define Vv   32000
#define FFf  2048
#define TOK  (Bn*Ss)

// ---------------- fp32 scratch ----------------
__device__ __align__(16) float g_x[TOK*Dd];
__device__ __align__(16) float g_y[TOK*Dd];
__device__ __align__(16) float g_tmp[TOK*Dd];

// ---------------- packed bf16x2 hi/lo ----------------
#define DD2  (Dd*Dd/2)
__device__ __align__(16) uint32_t g_encW_h[24*DD2], g_encW_l[24*DD2];
__device__ __align__(16) uint32_t g_decSW_h[24*DD2], g_decSW_l[24*DD2];
__device__ __align__(16) uint32_t g_decCW_h[24*DD2], g_decCW_l[24*DD2];
#define W1SZ (Dd*FFf/2)
__device__ __align__(16) uint32_t g_encW1_h[Nl*W1SZ], g_encW1_l[Nl*W1SZ];
__device__ __align__(16) uint32_t g_encW2_h[Nl*W1SZ], g_encW2_l[Nl*W1SZ];
__device__ __align__(16) uint32_t g_decW1_h[Nl*W1SZ], g_decW1_l[Nl*W1SZ];
__device__ __align__(16) uint32_t g_decW2_h[Nl*W1SZ], g_decW2_l[Nl*W1SZ];
#define OWSZ (Dd*Vv/2)
__device__ __align__(16) uint32_t g_outW_h[OWSZ], g_outW_l[OWSZ];
#define KVC  (TOK*Dd/2)
__device__ __align__(16) uint32_t g_xT_h[KVC],  g_xT_l[KVC];        // encoder-chain activation^T
__device__ __align__(16) uint32_t g_yT_h[KVC],  g_yT_l[KVC];        // decoder-chain activation^T
__device__ __align__(16) uint32_t g_qkvP_h[3*KVC], g_qkvP_l[3*KVC]; // q^T | k^T | vP
__device__ __align__(16) uint32_t g_oT_h[KVC],  g_oT_l[KVC];        // attn out^T
__device__ __align__(16) uint32_t g_xeT_h[KVC], g_xeT_l[KVC];       // encoder out^T
__device__ __align__(16) uint32_t g_xKV_h[12*KVC], g_xKV_l[12*KVC]; // cross K^T|V, 6 layers
#define FTSZ ((FFf/2)*TOK)
__device__ __align__(16) uint32_t g_fT_h[FTSZ], g_fT_l[FTSZ];       // ffn hidden^T

// ---------------- helpers ----------------
__device__ __forceinline__ void cvt_pair(float x0, float x1, uint32_t& hi, uint32_t& lo)
{
    uint32_t h;
    asm("cvt.rn.bf16x2.f32 %0, %1, %2;" : "=r"(h) : "f"(x1), "f"(x0));
    __nv_bfloat162 hb = *reinterpret_cast<__nv_bfloat162*>(&h);
    float r0 = x0 - __bfloat162float(hb.x);
    float r1 = x1 - __bfloat162float(hb.y);
    uint32_t l;
    asm("cvt.rn.bf16x2.f32 %0, %1, %2;" : "=r"(l) : "f"(r1), "f"(r0));
    hi = h; lo = l;
}

__device__ __forceinline__ uint32_t mulbf2(uint32_t a, uint32_t b)
{
    uint32_t d; asm("mul.rn.bf16x2 %0,%1,%2;" : "=r"(d) : "r"(a), "r"(b)); return d;
}

__device__ __forceinline__ void mma16816(float* c, const uint32_t* a, const uint32_t* b)
{
    asm volatile(
        "mma.sync.aligned.m16n8k16.row.col.f32.bf16.bf16.f32 "
        "{%0,%1,%2,%3}, {%4,%5,%6,%7}, {%8,%9}, {%0,%1,%2,%3};\n"
        : "+f"(c[0]), "+f"(c[1]), "+f"(c[2]), "+f"(c[3])
        : "r"(a[0]), "r"(a[1]), "r"(a[2]), "r"(a[3]), "r"(b[0]), "r"(b[1]));
}

__device__ __forceinline__ void cp_async16(uint32_t s, const void* g)
{
    asm volatile("cp.async.cg.shared.global [%0], [%1], 16;" :: "r"(s), "l"(g));
}
#define CP_COMMIT() asm volatile("cp.async.commit_group;")

__device__ __forceinline__ void cp_wait_n(int n)
{
    switch (n) {
    case 0: asm volatile("cp.async.wait_group 0;"); break;
    case 1: asm volatile("cp.async.wait_group 1;"); break;
    case 2: asm volatile("cp.async.wait_group 2;"); break;
    default: asm volatile("cp.async.wait_group 3;"); break;
    }
}

// ---------------- conversion kernels ----------------
__global__ __launch_bounds__(256)
void convB(const float* __restrict__ W, uint32_t* __restrict__ H,
           uint32_t* __restrict__ L, int C)
{
    long long kp = blockIdx.y;
    int c = blockIdx.x * 256 + threadIdx.x;
    float a = W[(2*kp) * (long long)C + c];
    float b = W[(2*kp+1) * (long long)C + c];
    uint32_t h, l; cvt_pair(a, b, h, l);
    long long o = kp * C + c;
    H[o] = h; L[o] = l;
}

// ---------------- all-packed mma.sync GEMM ----------------
// PACKMODE 0: C fp32 row-major
// PACKMODE 1: bf16x2 hi/lo transposed-packed [N/2][ldc]
// PACKMODE 3: per-z: zi < rThresh -> mode 1; else mode 2 (row-pair packed [M/2][ldc2])
template<int TBM, int TBN, int NTHREADS, int WARPS_M, int STAGES, int PACKMODE>
__global__ __launch_bounds__(NTHREADS)
void gemm_ap(const uint32_t* __restrict__ AH, const uint32_t* __restrict__ AL,
             const uint32_t* __restrict__ BH, const uint32_t* __restrict__ BL,
             const float* __restrict__ bias, float* __restrict__ C,
             uint32_t* __restrict__ CH, uint32_t* __restrict__ CL,
             int K, int ldap, int ldbp, int ldc, int ldc2,
             long long sAo, long long sAi, long long sBo, long long sBi,
             long long sCo, long long sCi, int Hsub, int rThresh,
             float alpha, int doBias, int doRelu)
{
    constexpr int WARPS   = NTHREADS / 32;
    constexpr int WARPS_N = WARPS / WARPS_M;
    constexpr int WM = TBM / WARPS_M;
    constexpr int WN = TBN / WARPS_N;
    constexpr int MT = WM / 16;
    constexpr int NT = WN / 8;
    constexpr int AS = TBM + 8;
    constexpr int BS = TBN + 8;
    constexpr int ASZ = 16 * AS;
    constexpr int BSZ = 16 * BS;
    constexpr int AC = (16 * (TBM / 4)) / NTHREADS;
    constexpr int BC = (16 * (TBN / 4)) / NTHREADS;

    extern __shared__ uint32_t smem[];
    uint32_t* sAh = smem;
    uint32_t* sAl = smem + STAGES * ASZ;
    uint32_t* sBh = smem + 2 * STAGES * ASZ;
    uint32_t* sBl = smem + 2 * STAGES * ASZ + STAGES * BSZ;

    int z = blockIdx.z;
    int zo = z / Hsub, zi = z % Hsub;
    const uint32_t* Ahb = AH + zo * sAo + zi * sAi;
    const uint32_t* Alb = AL + zo * sAo + zi * sAi;
    const uint32_t* Bhb = BH + zo * sBo + zi * sBi;
    const uint32_t* Blb = BL + zo * sBo + zi * sBi;
    float*    Cb  = (PACKMODE == 0) ? (C + zo * sCo + zi * sCi) : nullptr;
    uint32_t* CHb = (PACKMODE != 0) ? (CH + zo * sCo + zi * sCi) : nullptr;
    uint32_t* CLb = (PACKMODE != 0) ? (CL + zo * sCo + zi * sCi) : nullptr;

    int tid = threadIdx.x;
    int wid = tid >> 5, lane = tid & 31;
    int wm = wid % WARPS_M, wn = wid / WARPS_M;
    int group = lane >> 2, tig = lane & 3;
    int row0 = blockIdx.x * TBM;
    int col0 = blockIdx.y * TBN;

    auto cpStage = [&](int k0, int st) {
        int kp0 = k0 >> 1;
        uint32_t ah0 = (uint32_t)__cvta_generic_to_shared(sAh + st * ASZ);
        uint32_t al0 = (uint32_t)__cvta_generic_to_shared(sAl + st * ASZ);
#pragma unroll
        for (int j = 0; j < AC; j++) {
            int ci = tid + j * NTHREADS;
            int rr = ci / (TBM / 4), cc = ci % (TBM / 4);
            long long go = (long long)(kp0 + rr) * ldap + row0 + cc * 4;
            uint32_t so = (rr * AS + cc * 4) * 4;
            cp_async16(ah0 + so, Ahb + go);
            cp_async16(al0 + so, Alb + go);
        }
        uint32_t bh0 = (uint32_t)__cvta_generic_to_shared(sBh + st * BSZ);
        uint32_t bl0 = (uint32_t)__cvta_generic_to_shared(sBl + st * BSZ);
#pragma unroll
        for (int j = 0; j < BC; j++) {
            int ci = tid + j * NTHREADS;
            int rr = ci / (TBN / 4), cc = ci % (TBN / 4);
            long long go = (long long)(kp0 + rr) * ldbp + col0 + cc * 4;
            uint32_t so = (rr * BS + cc * 4) * 4;
            cp_async16(bh0 + so, Bhb + go);
            cp_async16(bl0 + so, Blb + go);
        }
        CP_COMMIT();
    };

    float acc[MT][NT][4];
#pragma unroll
    for (int i = 0; i < MT; i++)
#pragma unroll
        for (int j = 0; j < NT; j++)
#pragma unroll
            for (int t = 0; t < 4; t++) acc[i][j][t] = 0.f;

    int kpref = 0;
#pragma unroll
    for (int s = 0; s < STAGES - 1; s++) { cpStage(kpref, s); kpref += 32; }

    int st = 0;
    for (int k0 = 0; k0 < K; k0 += 32) {
        if (kpref < K) {
            cpStage(kpref, (kpref >> 5) % STAGES);
            kpref += 32;
        }
        cp_wait_n(((kpref - k0) >> 5) - 1);
        __syncthreads();

        const uint32_t* Ahs = sAh + st * ASZ;
        const uint32_t* Als = sAl + st * ASZ;
        const uint32_t* Bhs = sBh + st * BSZ;
        const uint32_t* Bls = sBl + st * BSZ;
#pragma unroll
        for (int ks = 0; ks < 2; ks++) {
            uint32_t ah[MT][4], al[MT][4], bh[NT][2], bl[NT][2];
            int kp0 = ks * 8 + tig, kp1 = kp0 + 4;
#pragma unroll
            for (int mt = 0; mt < MT; mt++) {
                int r = wm * WM + mt * 16 + group;
                ah[mt][0] = Ahs[kp0 * AS + r];     al[mt][0] = Als[kp0 * AS + r];
                ah[mt][1] = Ahs[kp0 * AS + r + 8]; al[mt][1] = Als[kp0 * AS + r + 8];
                ah[mt][2] = Ahs[kp1 * AS + r];     al[mt][2] = Als[kp1 * AS + r];
                ah[mt][3] = Ahs[kp1 * AS + r + 8]; al[mt][3] = Als[kp1 * AS + r + 8];
            }
#pragma unroll
            for (int nt = 0; nt < NT; nt++) {
                int c = wn * WN + nt * 8 + group;
                bh[nt][0] = Bhs[kp0 * BS + c];  bl[nt][0] = Bls[kp0 * BS + c];
                bh[nt][1] = Bhs[kp1 * BS + c];  bl[nt][1] = Bls[kp1 * BS + c];
            }
#pragma unroll
            for (int mt = 0; mt < MT; mt++)
#pragma unroll
                for (int nt = 0; nt < NT; nt++)
                    mma16816(acc[mt][nt], ah[mt], bh[nt]);
#pragma unroll
            for (int mt = 0; mt < MT; mt++)
#pragma unroll
                for (int nt = 0; nt < NT; nt++)
                    mma16816(acc[mt][nt], al[mt], bh[nt]);
#pragma unroll
            for (int mt = 0; mt < MT; mt++)
#pragma unroll
                for (int nt = 0; nt < NT; nt++)
                    mma16816(acc[mt][nt], ah[mt], bl[nt]);
        }
        __syncthreads();
        if (++st == STAGES) st = 0;
    }

    int effMode = (PACKMODE == 3) ? ((zi >= rThresh) ? 2 : 1) : PACKMODE;

#pragma unroll
    for (int mt = 0; mt < MT; mt++) {
        int r = row0 + wm * WM + mt * 16 + group;
#pragma unroll
        for (int nt = 0; nt < NT; nt++) {
            int c = col0 + wn * WN + nt * 8 + tig * 2;
            float v00 = acc[mt][nt][0] * alpha;
            float v01 = acc[mt][nt][1] * alpha;
            float v10 = acc[mt][nt][2] * alpha;
            float v11 = acc[mt][nt][3] * alpha;
            if (doBias) {
                float2 bb = *reinterpret_cast<const float2*>(&bias[c]);
                v00 += bb.x; v01 += bb.y; v10 += bb.x; v11 += bb.y;
            }
            if (doRelu) {
                v00 = fmaxf(v00, 0.f); v01 = fmaxf(v01, 0.f);
                v10 = fmaxf(v10, 0.f); v11 = fmaxf(v11, 0.f);
            }
            if (PACKMODE == 0) {
                *reinterpret_cast<float2*>(&Cb[(long long)r * ldc + c])       = make_float2(v00, v01);
                *reinterpret_cast<float2*>(&Cb[(long long)(r + 8) * ldc + c]) = make_float2(v10, v11);
            } else if (effMode == 1) {
                long long base = (long long)(c >> 1) * ldc + r;
                uint32_t h, l;
                cvt_pair(v00, v01, h, l); CHb[base] = h;     CLb[base] = l;
                cvt_pair(v10, v11, h, l); CHb[base + 8] = h; CLb[base + 8] = l;
            } else {
                float u00 = __shfl_down_sync(0xffffffffu, v00, 4);
                float u01 = __shfl_down_sync(0xffffffffu, v01, 4);
                float u10 = __shfl_down_sync(0xffffffffu, v10, 4);
                float u11 = __shfl_down_sync(0xffffffffu, v11, 4);
                if (!(group & 1)) {
                    long long b0 = (long long)(r >> 1) * ldc2 + c;
                    long long b8 = (long long)((r + 8) >> 1) * ldc2 + c;
                    uint32_t h, l;
                    cvt_pair(v00, u00, h, l); CHb[b0]     = h; CLb[b0]     = l;
                    cvt_pair(v01, u01, h, l); CHb[b0 + 1] = h; CLb[b0 + 1] = l;
                    cvt_pair(v10, u10, h, l); CHb[b8]     = h; CLb[b8]     = l;
                    cvt_pair(v11, u11, h, l); CHb[b8 + 1] = h; CLb[b8 + 1] = l;
                }
            }
        }
    }
}

// ---------------- fused flash attention ----------------
#define FA_STRIDE 68
#define FA_TSZ (32 * FA_STRIDE)
__global__ __launch_bounds__(128)
void flash_attn(const uint32_t* __restrict__ Qh, const uint32_t* __restrict__ Ql,
                const uint32_t* __restrict__ Kh, const uint32_t* __restrict__ Kl,
                const uint32_t* __restrict__ Vh, const uint32_t* __restrict__ Vl,
                uint32_t* __restrict__ Oh, uint32_t* __restrict__ Ol, int causal)
{
    extern __shared__ uint32_t smem[];
    uint32_t* sKh = smem;
    uint32_t* sKl = smem + 2 * FA_TSZ;
    uint32_t* sVh = smem + 4 * FA_TSZ;
    uint32_t* sVl = smem + 6 * FA_TSZ;

    int qb = blockIdx.x;
    int b  = blockIdx.y / Hh;
    int h  = blockIdx.y % Hh;
    int tid = threadIdx.x;
    int wid = tid >> 5, lane = tid & 31;
    int group = lane >> 2, tig = lane & 3;
    int tokBase = b * Ss + qb * 64 + wid * 16;

    uint32_t qh[4][4], ql[4][4];
    const uint32_t SC = 0x3E003E00u;
#pragma unroll
    for (int ks = 0; ks < 4; ks++) {
        int kpa = h * 32 + ks * 8 + tig;
        long long b0 = (long long)kpa * TOK + tokBase + group;
        long long b2 = (long long)(kpa + 4) * TOK + tokBase + group;
        qh[ks][0] = mulbf2(Qh[b0], SC);     ql[ks][0] = mulbf2(Ql[b0], SC);
        qh[ks][1] = mulbf2(Qh[b0 + 8], SC); ql[ks][1] = mulbf2(Ql[b0 + 8], SC);
        qh[ks][2] = mulbf2(Qh[b2], SC);     ql[ks][2] = mulbf2(Ql[b2], SC);
        qh[ks][3] = mulbf2(Qh[b2 + 8], SC); ql[ks][3] = mulbf2(Ql[b2 + 8], SC);
    }

    float m0 = -INFINITY, m1 = -INFINITY, l0 = 0.f, l1 = 0.f;
    float acc_o[8][4];
#pragma unroll
    for (int nt = 0; nt < 8; nt++)
#pragma unroll
        for (int t = 0; t < 4; t++) acc_o[nt][t] = 0.f;

    int nkb = causal ? (qb + 1) : (Ss / 64);

    auto cpStage = [&](int kb, int stg) {
        uint32_t kh0 = (uint32_t)__cvta_generic_to_shared(sKh + stg * FA_TSZ);
        uint32_t kl0 = (uint32_t)__cvta_generic_to_shared(sKl + stg * FA_TSZ);
        uint32_t vh0 = (uint32_t)__cvta_generic_to_shared(sVh + stg * FA_TSZ);
        uint32_t vl0 = (uint32_t)__cvta_generic_to_shared(sVl + stg * FA_TSZ);
#pragma unroll
        for (int i = 0; i < 4; i++) {
            int idx = tid + i * 128;
            int row = idx >> 4, c4 = idx & 15;
            uint32_t so = (row * FA_STRIDE + c4 * 4) * 4;
            long long gK = (long long)(h * 32 + row) * TOK + b * Ss + kb * 64 + c4 * 4;
            cp_async16(kh0 + so, Kh + gK);
            cp_async16(kl0 + so, Kl + gK);
            long long gV = (long long)(b * (Ss / 2) + kb * 32 + row) * Dd + h * 64 + c4 * 4;
            cp_async16(vh0 + so, Vh + gV);
            cp_async16(vl0 + so, Vl + gV);
        }
        CP_COMMIT();
    };

    cpStage(0, 0);
    for (int kb = 0; kb < nkb; kb++) {
        if (kb + 1 < nkb) {
            cpStage(kb + 1, (kb + 1) & 1);
            asm volatile("cp.async.wait_group 1;");
        } else {
            asm volatile("cp.async.wait_group 0;");
        }
        __syncthreads();
        int stg = kb & 1;
        const uint32_t* Ksh = sKh + stg * FA_TSZ;
        const uint32_t* Ksl = sKl + stg * FA_TSZ;
        const uint32_t* Vsh = sVh + stg * FA_TSZ;
        const uint32_t* Vsl = sVl + stg * FA_TSZ;

        float s[8][4];
#pragma unroll
        for (int nt = 0; nt < 8; nt++)
#pragma unroll
            for (int t = 0; t < 4; t++) s[nt][t] = 0.f;
#pragma unroll
        for (int ks = 0; ks < 4; ks++) {
            int r0 = (ks * 8 + tig) * FA_STRIDE, r1 = r0 + 4 * FA_STRIDE;
            uint32_t bhf[8][2], blf[8][2];
#pragma unroll
            for (int nt = 0; nt < 8; nt++) {
                int c = nt * 8 + group;
                bhf[nt][0] = Ksh[r0 + c]; bhf[nt][1] = Ksh[r1 + c];
                blf[nt][0] = Ksl[r0 + c]; blf[nt][1] = Ksl[r1 + c];
            }
#pragma unroll
            for (int nt = 0; nt < 8; nt++) mma16816(s[nt], qh[ks], bhf[nt]);
#pragma unroll
            for (int nt = 0; nt < 8; nt++) mma16816(s[nt], ql[ks], bhf[nt]);
#pragma unroll
            for (int nt = 0; nt < 8; nt++) mma16816(s[nt], qh[ks], blf[nt]);
        }

        if (causal && kb == qb) {
            int r0 = wid * 16 + group, r1 = r0 + 8;
#pragma unroll
            for (int nt = 0; nt < 8; nt++) {
                int c0 = nt * 8 + tig * 2;
                if (c0     > r0) s[nt][0] = -1e9f;
                if (c0 + 1 > r0) s[nt][1] = -1e9f;
                if (c0     > r1) s[nt][2] = -1e9f;
                if (c0 + 1 > r1) s[nt][3] = -1e9f;
            }
        }

        float bm0 = -INFINITY, bm1 = -INFINITY;
#pragma unroll
        for (int nt = 0; nt < 8; nt++) {
            bm0 = fmaxf(bm0, fmaxf(s[nt][0], s[nt][1]));
            bm1 = fmaxf(bm1, fmaxf(s[nt][2], s[nt][3]));
        }
        bm0 = fmaxf(bm0, __shfl_xor_sync(0xffffffffu, bm0, 1));
        bm0 = fmaxf(bm0, __shfl_xor_sync(0xffffffffu, bm0, 2));
        bm1 = fmaxf(bm1, __shfl_xor_sync(0xffffffffu, bm1, 1));
        bm1 = fmaxf(bm1, __shfl_xor_sync(0xffffffffu, bm1, 2));
        float nm0 = fmaxf(m0, bm0), nm1 = fmaxf(m1, bm1);
        float a0f = __expf(m0 - nm0), a1f = __expf(m1 - nm1);
        m0 = nm0; m1 = nm1;
        float rs0 = 0.f, rs1 = 0.f;
#pragma unroll
        for (int nt = 0; nt < 8; nt++) {
            s[nt][0] = __expf(s[nt][0] - nm0);
            s[nt][1] = __expf(s[nt][1] - nm0);
            s[nt][2] = __expf(s[nt][2] - nm1);
            s[nt][3] = __expf(s[nt][3] - nm1);
            rs0 += s[nt][0] + s[nt][1];
            rs1 += s[nt][2] + s[nt][3];
        }
        rs0 += __shfl_xor_sync(0xffffffffu, rs0, 1);
        rs0 += __shfl_xor_sync(0xffffffffu, rs0, 2);
        rs1 += __shfl_xor_sync(0xffffffffu, rs1, 1);
        rs1 += __shfl_xor_sync(0xffffffffu, rs1, 2);
        l0 = l0 * a0f + rs0;
        l1 = l1 * a1f + rs1;
#pragma unroll
        for (int nt = 0; nt < 8; nt++) {
            acc_o[nt][0] *= a0f; acc_o[nt][1] *= a0f;
            acc_o[nt][2] *= a1f; acc_o[nt][3] *= a1f;
        }

        uint32_t ph[4][4], pl[4][4];
#pragma unroll
        for (int j = 0; j < 4; j++) {
            cvt_pair(s[2*j  ][0], s[2*j  ][1], ph[j][0], pl[j][0]);
            cvt_pair(s[2*j  ][2], s[2*j  ][3], ph[j][1], pl[j][1]);
            cvt_pair(s[2*j+1][0], s[2*j+1][1], ph[j][2], pl[j][2]);
            cvt_pair(s[2*j+1][2], s[2*j+1][3], ph[j][3], pl[j][3]);
        }

#pragma unroll
        for (int j = 0; j < 4; j++) {
            int r0 = (j * 8 + tig) * FA_STRIDE, r1 = r0 + 4 * FA_STRIDE;
            uint32_t vbh[8][2], vbl[8][2];
#pragma unroll
            for (int nt = 0; nt < 8; nt++) {
                int c = nt * 8 + group;
                vbh[nt][0] = Vsh[r0 + c]; vbh[nt][1] = Vsh[r1 + c];
                vbl[nt][0] = Vsl[r0 + c]; vbl[nt][1] = Vsl[r1 + c];
            }
#pragma unroll
            for (int nt = 0; nt < 8; nt++) mma16816(acc_o[nt], ph[j], vbh[nt]);
#pragma unroll
            for (int nt = 0; nt < 8; nt++) mma16816(acc_o[nt], pl[j], vbh[nt]);
#pragma unroll
            for (int nt = 0; nt < 8; nt++) mma16816(acc_o[nt], ph[j], vbl[nt]);
        }
        __syncthreads();
    }

    float inv0 = 1.0f / l0, inv1 = 1.0f / l1;
#pragma unroll
    for (int nt = 0; nt < 8; nt++) {
        int cp = h * 32 + nt * 4 + tig;
        long long bo = (long long)cp * TOK + tokBase + group;
        uint32_t hh, ll;
        cvt_pair(acc_o[nt][0] * inv0, acc_o[nt][1] * inv0, hh, ll);
        Oh[bo] = hh; Ol[bo] = ll;
        cvt_pair(acc_o[nt][2] * inv1, acc_o[nt][3] * inv1, hh, ll);
        Oh[bo + 8] = hh; Ol[bo + 8] = ll;
    }
}

// ---------------- vocab softmax ----------
__global__ __launch_bounds__(1024)
void softmax_vocab(float* __restrict__ P)
{
    float* p = P + (long long)blockIdx.x * Vv;
    int t = threadIdx.x;
    __shared__ float red[32];
    float v[32];
    float mx = -3.0e38f;
#pragma unroll
    for (int i = 0; i < 32; i++) {
        int idx = t + i * 1024;
        v[i] = (idx < Vv) ? p[idx] : -3.0e38f;
        mx = fmaxf(mx, v[i]);
    }
    for (int o = 16; o; o >>= 1) mx = fmaxf(mx, __shfl_xor_sync(0xffffffffu, mx, o));
    if ((t & 31) == 0) red[t >> 5] = mx;
    __syncthreads();
    if (t < 32) {
        float m2 = red[t];
        for (int o = 16; o; o >>= 1) m2 = fmaxf(m2, __shfl_xor_sync(0xffffffffu, m2, o));
        if (t == 0) red[0] = m2;
    }
    __syncthreads();
    mx = red[0];
    __syncthreads();
    float sum = 0.f;
#pragma unroll
    for (int i = 0; i < 32; i++) { v[i] = __expf(v[i] - mx); sum += v[i]; }
    for (int o = 16; o; o >>= 1) sum += __shfl_xor_sync(0xffffffffu, sum, o);
    if ((t & 31) == 0) red[t >> 5] = sum;
    __syncthreads();
    if (t < 32) {
        float s2 = red[t];
        for (int o = 16; o; o >>= 1) s2 += __shfl_xor_sync(0xffffffffu, s2, o);
        if (t == 0) red[0] = s2;
    }
    __syncthreads();
    float inv = 1.0f / red[0];
#pragma unroll
    for (int i = 0; i < 32; i++) {
        int idx = t + i * 1024;
        if (idx < Vv) p[idx] = v[i] * inv;
    }
}

// ---------------- fused add + LayerNorm + COALESCED transposed pack ----------
// 8 rows per block, one warp per row (warp-shuffle LN), smem-staged transpose write.
__global__ __launch_bounds__(256)
void add_ln_pack8(float* __restrict__ x, const float* __restrict__ sub,
                  uint32_t* __restrict__ H, uint32_t* __restrict__ L)
{
    __shared__ uint32_t sH[8][260];
    __shared__ uint32_t sL[8][260];
    int w = threadIdx.x >> 5, lane = threadIdx.x & 31;
    int row = blockIdx.x * 8 + w;
    float* xr = x + (long long)row * Dd;
    const float* sr = sub + (long long)row * Dd;

    float2 v[8];
    float sum = 0.f;
#pragma unroll
    for (int j = 0; j < 8; j++) {
        float2 a = *reinterpret_cast<const float2*>(xr + 2 * lane + 64 * j);
        float2 b = *reinterpret_cast<const float2*>(sr + 2 * lane + 64 * j);
        v[j].x = a.x + b.x;
        v[j].y = a.y + b.y;
        sum += v[j].x + v[j].y;
    }
    for (int o = 16; o; o >>= 1) sum += __shfl_xor_sync(0xffffffffu, sum, o);
    float mu = sum * (1.0f / 512.0f);
    float var = 0.f;
#pragma unroll
    for (int j = 0; j < 8; j++) {
        v[j].x -= mu; v[j].y -= mu;
        var += v[j].x * v[j].x + v[j].y * v[j].y;
    }
    for (int o = 16; o; o >>= 1) var += __shfl_xor_sync(0xffffffffu, var, o);
    float inv = rsqrtf(var * (1.0f / 512.0f) + 1e-5f);
#pragma unroll
    for (int j = 0; j < 8; j++) {
        v[j].x *= inv; v[j].y *= inv;
        *reinterpret_cast<float2*>(xr + 2 * lane + 64 * j) = v[j];
        uint32_t h, l; cvt_pair(v[j].x, v[j].y, h, l);
        sH[w][lane + 32 * j] = h;
        sL[w][lane + 32 * j] = l;
    }
    __syncthreads();
    int row0 = blockIdx.x * 8;
#pragma unroll
    for (int i = 0; i < 8; i++) {
        int idx = threadIdx.x + i * 256;
        int kp = idx >> 3, r = idx & 7;
        long long o = (long long)kp * TOK + row0 + r;
        H[o] = sH[r][kp];
        L[o] = sL[r][kp];
    }
}

// ---------------- embedding + PE + transposed pack ----------
__global__ __launch_bounds__(512)
void embed_pe_pack(const int* __restrict__ tok, const float* __restrict__ emb,
                   float* __restrict__ out,
                   uint32_t* __restrict__ H, uint32_t* __restrict__ L)
{
    int idx = blockIdx.x;
    int s = idx % Ss;
    int j = threadIdx.x;
    int tk = tok[idx];
    float ang = (float)s * powf(10000.0f, -2.0f * (float)j / 512.0f);
    float pe = (j & 1) ? cosf(ang) : sinf(ang);
    float v = emb[(long long)tk * Dd + j] + pe;
    out[(long long)idx * Dd + j] = v;

    float p = __shfl_down_sync(0xffffffffu, v, 1);
    if (!(j & 1)) {
        uint32_t h, l;
        cvt_pair(v, p, h, l);
        long long o = (long long)(j >> 1) * TOK + idx;
        H[o] = h; L[o] = l;
    }
}

// ---------------- host ----------------
static const int SM_AP64_3  = (4 * 3 * 16 * (64 + 8)) * 4;     // 55,296
static const int SM_AP128_3 = (4 * 3 * 16 * (128 + 8)) * 4;    // 104,448
static const int SM_FA      = 8 * FA_TSZ * 4;                  // 69,632

struct GPtrs {
    float *x, *y, *tmp;
    uint32_t *encWh, *encWl, *decSWh, *decSWl, *decCWh, *decCWl;
    uint32_t *eW1h, *eW1l, *eW2h, *eW2l, *dW1h, *dW1l, *dW2h, *dW2l;
    uint32_t *oWh, *oWl;
    uint32_t *xTh, *xTl, *yTh, *yTl, *qkvPh, *qkvPl, *oTh, *oTl;
    uint32_t *xeTh, *xeTl, *xKVh, *xKVl, *fTh, *fTl;
};

static void run_mha_self(GPtrs& G, const uint32_t* aTh, const uint32_t* aTl,
                         const uint32_t* wh, const uint32_t* wl, float* out, bool causal)
{
    {
        dim3 g(TOK/64, Dd/64, 3);
        gemm_ap<64,64,128,2,3,3><<<g, 128, SM_AP64_3>>>(aTh, aTl, wh, wl,
            nullptr, nullptr, G.qkvPh, G.qkvPl,
            Dd, TOK, Dd, TOK, Dd,
            0, 0, 0, DD2, 0, KVC, 3, 2, 1.0f, 0, 0);
    }
    flash_attn<<<dim3(Ss/64, Bn*Hh), 128, SM_FA>>>(
        G.qkvPh, G.qkvPl, G.qkvPh + KVC, G.qkvPl + KVC,
        G.qkvPh + 2*KVC, G.qkvPl + 2*KVC, G.oTh, G.oTl, causal ? 1 : 0);
    {
        dim3 g(TOK/64, Dd/64, 1);
        gemm_ap<64,64,128,2,3,0><<<g, 128, SM_AP64_3>>>(G.oTh, G.oTl, wh + 3*DD2, wl + 3*DD2,
            nullptr, out, nullptr, nullptr,
            Dd, TOK, Dd, Dd, Dd,
            0, 0, 0, 0, 0, 0, 1, 0, 1.0f, 0, 0);
    }
}

static void run_mha_cross(GPtrs& G, const uint32_t* aTh, const uint32_t* aTl, int layer,
                          const uint32_t* wh, const uint32_t* wl, float* out)
{
    {
        dim3 g(TOK/64, Dd/64, 1);
        gemm_ap<64,64,128,2,3,1><<<g, 128, SM_AP64_3>>>(aTh, aTl, wh, wl,
            nullptr, nullptr, G.qkvPh, G.qkvPl,
            Dd, TOK, Dd, TOK, Dd,
            0, 0, 0, 0, 0, 0, 1, 0, 1.0f, 0, 0);
    }
    const uint32_t* kh = G.xKVh + (long long)layer * 2 * KVC;
    const uint32_t* kl = G.xKVl + (long long)layer * 2 * KVC;
    flash_attn<<<dim3(Ss/64, Bn*Hh), 128, SM_FA>>>(
        G.qkvPh, G.qkvPl, kh, kl, kh + KVC, kl + KVC, G.oTh, G.oTl, 0);
    {
        dim3 g(TOK/64, Dd/64, 1);
        gemm_ap<64,64,128,2,3,0><<<g, 128, SM_AP64_3>>>(G.oTh, G.oTl, wh + 3*DD2, wl + 3*DD2,
            nullptr, out, nullptr, nullptr,
            Dd, TOK, Dd, Dd, Dd,
            0, 0, 0, 0, 0, 0, 1, 0, 1.0f, 0, 0);
    }
}

static void run_ffn(GPtrs& G, const uint32_t* aTh, const uint32_t* aTl,
                    const uint32_t* w1h, const uint32_t* w1l, const float* b1,
                    const uint32_t* w2h, const uint32_t* w2l, const float* b2)
{
    {
        dim3 g(TOK/128, FFf/128, 1);
        gemm_ap<128,128,256,4,3,1><<<g, 256, SM_AP128_3>>>(aTh, aTl, w1h, w1l,
            b1, nullptr, G.fTh, G.fTl,
            Dd, TOK, FFf, TOK, Dd,
            0, 0, 0, 0, 0, 0, 1, 0, 1.0f, 1, 1);
    }
    {
        dim3 g(TOK/64, Dd/64, 1);
        gemm_ap<64,64,128,2,3,0><<<g, 128, SM_AP64_3>>>(G.fTh, G.fTl, w2h, w2l,
            b2, G.tmp, nullptr, nullptr,
            FFf, TOK, Dd, Dd, Dd,
            0, 0, 0, 0, 0, 0, 1, 0, 1.0f, 1, 0);
    }
}

extern "C" void kernel_launch(void* const* d_in, const int* in_sizes, int n_in,
                              void* d_out, int out_size)
{
    const int*   src           = (const int*)  d_in[0];
    const int*   trg           = (const int*)  d_in[1];
    const float* src_emb       = (const float*)d_in[2];
    const float* trg_emb       = (const float*)d_in[3];
    const float* enc_qkvo      = (const float*)d_in[4];
    const float* enc_ffn_w1    = (const float*)d_in[5];
    const float* enc_ffn_b1    = (const float*)d_in[6];
    const float* enc_ffn_w2    = (const float*)d_in[7];
    const float* enc_ffn_b2    = (const float*)d_in[8];
    const float* dec_self_qkvo = (const float*)d_in[9];
    const float* dec_cross_qkvo= (const float*)d_in[10];
    const float* dec_ffn_w1    = (const float*)d_in[11];
    const float* dec_ffn_b1    = (const float*)d_in[12];
    const float* dec_ffn_w2    = (const float*)d_in[13];
    const float* dec_ffn_b2    = (const float*)d_in[14];
    const float* out_w         = (const float*)d_in[15];
    const float* out_b         = (const float*)d_in[16];
    float* out = (float*)d_out;

    cudaFuncSetAttribute(gemm_ap<64,64,128,2,3,0>,
                         cudaFuncAttributeMaxDynamicSharedMemorySize, SM_AP64_3);
    cudaFuncSetAttribute(gemm_ap<64,64,128,2,3,1>,
                         cudaFuncAttributeMaxDynamicSharedMemorySize, SM_AP64_3);
    cudaFuncSetAttribute(gemm_ap<64,64,128,2,3,3>,
                         cudaFuncAttributeMaxDynamicSharedMemorySize, SM_AP64_3);
    cudaFuncSetAttribute(gemm_ap<128,128,256,4,3,0>,
                         cudaFuncAttributeMaxDynamicSharedMemorySize, SM_AP128_3);
    cudaFuncSetAttribute(gemm_ap<128,128,256,4,3,1>,
                         cudaFuncAttributeMaxDynamicSharedMemorySize, SM_AP128_3);
    cudaFuncSetAttribute(flash_attn,
                         cudaFuncAttributeMaxDynamicSharedMemorySize, SM_FA);

    GPtrs G;
    cudaGetSymbolAddress((void**)&G.x,    g_x);
    cudaGetSymbolAddress((void**)&G.y,    g_y);
    cudaGetSymbolAddress((void**)&G.tmp,  g_tmp);
    cudaGetSymbolAddress((void**)&G.encWh,  g_encW_h);  cudaGetSymbolAddress((void**)&G.encWl, g_encW_l);
    cudaGetSymbolAddress((void**)&G.decSWh, g_decSW_h); cudaGetSymbolAddress((void**)&G.decSWl, g_decSW_l);
    cudaGetSymbolAddress((void**)&G.decCWh, g_decCW_h); cudaGetSymbolAddress((void**)&G.decCWl, g_decCW_l);
    cudaGetSymbolAddress((void**)&G.eW1h,   g_encW1_h); cudaGetSymbolAddress((void**)&G.eW1l, g_encW1_l);
    cudaGetSymbolAddress((void**)&G.eW2h,   g_encW2_h); cudaGetSymbolAddress((void**)&G.eW2l, g_encW2_l);
    cudaGetSymbolAddress((void**)&G.dW1h,   g_decW1_h); cudaGetSymbolAddress((void**)&G.dW1l, g_decW1_l);
    cudaGetSymbolAddress((void**)&G.dW2h,   g_decW2_h); cudaGetSymbolAddress((void**)&G.dW2l, g_decW2_l);
    cudaGetSymbolAddress((void**)&G.oWh,    g_outW_h);  cudaGetSymbolAddress((void**)&G.oWl, g_outW_l);
    cudaGetSymbolAddress((void**)&G.xTh,    g_xT_h);    cudaGetSymbolAddress((void**)&G.xTl, g_xT_l);
    cudaGetSymbolAddress((void**)&G.yTh,    g_yT_h);    cudaGetSymbolAddress((void**)&G.yTl, g_yT_l);
    cudaGetSymbolAddress((void**)&G.qkvPh,  g_qkvP_h);  cudaGetSymbolAddress((void**)&G.qkvPl, g_qkvP_l);
    cudaGetSymbolAddress((void**)&G.oTh,    g_oT_h);    cudaGetSymbolAddress((void**)&G.oTl, g_oT_l);
    cudaGetSymbolAddress((void**)&G.xeTh,   g_xeT_h);   cudaGetSymbolAddress((void**)&G.xeTl, g_xeT_l);
    cudaGetSymbolAddress((void**)&G.xKVh,   g_xKV_h);   cudaGetSymbolAddress((void**)&G.xKVl, g_xKV_l);
    cudaGetSymbolAddress((void**)&G.fTh,    g_fT_h);    cudaGetSymbolAddress((void**)&G.fTl, g_fT_l);

    // weight conversions (once per call)
    convB<<<dim3(Dd / 256,  24 * Dd / 2), 256>>>(enc_qkvo,       G.encWh, G.encWl, Dd);
    convB<<<dim3(Dd / 256,  24 * Dd / 2), 256>>>(dec_self_qkvo,  G.decSWh, G.decSWl, Dd);
    convB<<<dim3(Dd / 256,  24 * Dd / 2), 256>>>(dec_cross_qkvo, G.decCWh, G.decCWl, Dd);
    convB<<<dim3(FFf / 256, Nl * Dd / 2), 256>>>(enc_ffn_w1, G.eW1h, G.eW1l, FFf);
    convB<<<dim3(Dd / 256,  Nl * FFf / 2), 256>>>(enc_ffn_w2, G.eW2h, G.eW2l, Dd);
    convB<<<dim3(FFf / 256, Nl * Dd / 2), 256>>>(dec_ffn_w1, G.dW1h, G.dW1l, FFf);
    convB<<<dim3(Dd / 256,  Nl * FFf / 2), 256>>>(dec_ffn_w2, G.dW2h, G.dW2l, Dd);
    convB<<<dim3(Vv / 256,  Dd / 2), 256>>>(out_w, G.oWh, G.oWl, Vv);

    embed_pe_pack<<<TOK, 512>>>(src, src_emb, G.x, G.xTh, G.xTl);
    embed_pe_pack<<<TOK, 512>>>(trg, trg_emb, G.y, G.yTh, G.yTl);

    // ---------------- Encoder ----------------
    for (int i = 0; i < Nl; i++) {
        run_mha_self(G, G.xTh, G.xTl,
                G.encWh + (long long)i * 4 * DD2, G.encWl + (long long)i * 4 * DD2,
                G.tmp, false);
        add_ln_pack8<<<TOK/8, 256>>>(G.x, G.tmp, G.xTh, G.xTl);
        run_ffn(G, G.xTh, G.xTl,
                G.eW1h + (long long)i * W1SZ, G.eW1l + (long long)i * W1SZ,
                enc_ffn_b1 + (long long)i * FFf,
                G.eW2h + (long long)i * W1SZ, G.eW2l + (long long)i * W1SZ,
                enc_ffn_b2 + (long long)i * Dd);
        if (i == Nl - 1)
            add_ln_pack8<<<TOK/8, 256>>>(G.x, G.tmp, G.xeTh, G.xeTl);
        else
            add_ln_pack8<<<TOK/8, 256>>>(G.x, G.tmp, G.xTh, G.xTl);
    }

    // precompute ALL cross-attn K,V (6 layers) from packed encoder output
    {
        dim3 g(TOK/64, Dd/64, 2 * Nl);
        gemm_ap<64,64,128,2,3,3><<<g, 128, SM_AP64_3>>>(G.xeTh, G.xeTl,
            G.decCWh + DD2, G.decCWl + DD2,
            nullptr, nullptr, G.xKVh, G.xKVl,
            Dd, TOK, Dd, TOK, Dd,
            0, 0, (long long)4 * DD2, DD2, (long long)2 * KVC, KVC,
            2, 1, 1.0f, 0, 0);
    }

    // ---------------- Decoder ----------------
    for (int i = 0; i < Nl; i++) {
        run_mha_self(G, G.yTh, G.yTl,
                G.decSWh + (long long)i * 4 * DD2, G.decSWl + (long long)i * 4 * DD2,
                G.tmp, true);
        add_ln_pack8<<<TOK/8, 256>>>(G.y, G.tmp, G.yTh, G.yTl);

        run_mha_cross(G, G.yTh, G.yTl, i,
                G.decCWh + (long long)i * 4 * DD2, G.decCWl + (long long)i * 4 * DD2,
                G.tmp);
        add_ln_pack8<<<TOK/8, 256>>>(G.y, G.tmp, G.yTh, G.yTl);

        run_ffn(G, G.yTh, G.yTl,
                G.dW1h + (long long)i * W1SZ, G.dW1l + (long long)i * W1SZ,
                dec_ffn_b1 + (long long)i * FFf,
                G.dW2h + (long long)i * W1SZ, G.dW2l + (long long)i * W1SZ,
                dec_ffn_b2 + (long long)i * Dd);
        add_ln_pack8<<<TOK/8, 256>>>(G.y, G.tmp, G.yTh, G.yTl);
    }

    // ---------------- Output projection + vocab softmax ----------------
    {
        dim3 g(TOK/128, Vv/128, 1);
        gemm_ap<128,128,256,4,3,0><<<g, 256, SM_AP128_3>>>(G.yTh, G.yTl, G.oWh, G.oWl,
            out_b, out, nullptr, nullptr,
            Dd, TOK, Vv, Vv, Dd,
            0, 0, 0, 0, 0, 0, 1, 0, 1.0f, 1, 0);
    }
    softmax_vocab<<<TOK, 1024>>>(out);
}

// round 17
// speedup vs baseline: 1.1512x; 1.0079x over previous
#include <cuda_runtime.h>
#include <cuda_bf16.h>
#include <math.h>
#include <stdint.h>

#define Bn   4
#define Ss   512
#define Dd   512
#define Hh   8
#define DKk  64
#define Nl   6
#define Vv   32000
#define FFf  2048
#define TOK  (Bn*Ss)
#define TD   ((long long)TOK*Dd)

// ---------------- fp32 scratch ----------------
__device__ __align__(16) float g_x[TOK*Dd];
__device__ __align__(16) float g_y[TOK*Dd];
__device__ __align__(16) float g_tmp[2*TOK*Dd];   // split-K partial slices

// ---------------- packed bf16x2 hi/lo ----------------
#define DD2  (Dd*Dd/2)
__device__ __align__(16) uint32_t g_encW_h[24*DD2], g_encW_l[24*DD2];
__device__ __align__(16) uint32_t g_decSW_h[24*DD2], g_decSW_l[24*DD2];
__device__ __align__(16) uint32_t g_decCW_h[24*DD2], g_decCW_l[24*DD2];
#define W1SZ (Dd*FFf/2)
__device__ __align__(16) uint32_t g_encW1_h[Nl*W1SZ], g_encW1_l[Nl*W1SZ];
__device__ __align__(16) uint32_t g_encW2_h[Nl*W1SZ], g_encW2_l[Nl*W1SZ];
__device__ __align__(16) uint32_t g_decW1_h[Nl*W1SZ], g_decW1_l[Nl*W1SZ];
__device__ __align__(16) uint32_t g_decW2_h[Nl*W1SZ], g_decW2_l[Nl*W1SZ];
#define OWSZ (Dd*Vv/2)
__device__ __align__(16) uint32_t g_outW_h[OWSZ], g_outW_l[OWSZ];
#define KVC  (TOK*Dd/2)
__device__ __align__(16) uint32_t g_xT_h[KVC],  g_xT_l[KVC];
__device__ __align__(16) uint32_t g_yT_h[KVC],  g_yT_l[KVC];
__device__ __align__(16) uint32_t g_qkvP_h[3*KVC], g_qkvP_l[3*KVC];
__device__ __align__(16) uint32_t g_oT_h[KVC],  g_oT_l[KVC];
__device__ __align__(16) uint32_t g_xeT_h[KVC], g_xeT_l[KVC];
__device__ __align__(16) uint32_t g_xKV_h[12*KVC], g_xKV_l[12*KVC];
#define FTSZ ((FFf/2)*TOK)
__device__ __align__(16) uint32_t g_fT_h[FTSZ], g_fT_l[FTSZ];

// ---------------- helpers ----------------
__device__ __forceinline__ void cvt_pair(float x0, float x1, uint32_t& hi, uint32_t& lo)
{
    uint32_t h;
    asm("cvt.rn.bf16x2.f32 %0, %1, %2;" : "=r"(h) : "f"(x1), "f"(x0));
    __nv_bfloat162 hb = *reinterpret_cast<__nv_bfloat162*>(&h);
    float r0 = x0 - __bfloat162float(hb.x);
    float r1 = x1 - __bfloat162float(hb.y);
    uint32_t l;
    asm("cvt.rn.bf16x2.f32 %0, %1, %2;" : "=r"(l) : "f"(r1), "f"(r0));
    hi = h; lo = l;
}

__device__ __forceinline__ uint32_t mulbf2(uint32_t a, uint32_t b)
{
    uint32_t d; asm("mul.rn.bf16x2 %0,%1,%2;" : "=r"(d) : "r"(a), "r"(b)); return d;
}

__device__ __forceinline__ void mma16816(float* c, const uint32_t* a, const uint32_t* b)
{
    asm volatile(
        "mma.sync.aligned.m16n8k16.row.col.f32.bf16.bf16.f32 "
        "{%0,%1,%2,%3}, {%4,%5,%6,%7}, {%8,%9}, {%0,%1,%2,%3};\n"
        : "+f"(c[0]), "+f"(c[1]), "+f"(c[2]), "+f"(c[3])
        : "r"(a[0]), "r"(a[1]), "r"(a[2]), "r"(a[3]), "r"(b[0]), "r"(b[1]));
}

__device__ __forceinline__ void cp_async16(uint32_t s, const void* g)
{
    asm volatile("cp.async.cg.shared.global [%0], [%1], 16;" :: "r"(s), "l"(g));
}
#define CP_COMMIT() asm volatile("cp.async.commit_group;")

__device__ __forceinline__ void cp_wait_n(int n)
{
    switch (n) {
    case 0: asm volatile("cp.async.wait_group 0;"); break;
    case 1: asm volatile("cp.async.wait_group 1;"); break;
    case 2: asm volatile("cp.async.wait_group 2;"); break;
    default: asm volatile("cp.async.wait_group 3;"); break;
    }
}

// ---------------- conversion kernels ----------------
__global__ __launch_bounds__(256)
void convB(const float* __restrict__ W, uint32_t* __restrict__ H,
           uint32_t* __restrict__ L, int C)
{
    long long kp = blockIdx.y;
    int c = blockIdx.x * 256 + threadIdx.x;
    float a = W[(2*kp) * (long long)C + c];
    float b = W[(2*kp+1) * (long long)C + c];
    uint32_t h, l; cvt_pair(a, b, h, l);
    long long o = kp * C + c;
    H[o] = h; L[o] = l;
}

// ---------------- all-packed mma.sync GEMM ----------------
// PACKMODE 0: C fp32 row-major
// PACKMODE 1: bf16x2 hi/lo transposed-packed [N/2][ldc]
// PACKMODE 3: per-z: zi < rThresh -> mode 1; else mode 2 (row-pair packed [M/2][ldc2])
template<int TBM, int TBN, int NTHREADS, int WARPS_M, int STAGES, int PACKMODE>
__global__ __launch_bounds__(NTHREADS)
void gemm_ap(const uint32_t* __restrict__ AH, const uint32_t* __restrict__ AL,
             const uint32_t* __restrict__ BH, const uint32_t* __restrict__ BL,
             const float* __restrict__ bias, float* __restrict__ C,
             uint32_t* __restrict__ CH, uint32_t* __restrict__ CL,
             int K, int ldap, int ldbp, int ldc, int ldc2,
             long long sAo, long long sAi, long long sBo, long long sBi,
             long long sCo, long long sCi, int Hsub, int rThresh,
             float alpha, int doBias, int doRelu)
{
    constexpr int WARPS   = NTHREADS / 32;
    constexpr int WARPS_N = WARPS / WARPS_M;
    constexpr int WM = TBM / WARPS_M;
    constexpr int WN = TBN / WARPS_N;
    constexpr int MT = WM / 16;
    constexpr int NT = WN / 8;
    constexpr int AS = TBM + 8;
    constexpr int BS = TBN + 8;
    constexpr int ASZ = 16 * AS;
    constexpr int BSZ = 16 * BS;
    constexpr int AC = (16 * (TBM / 4)) / NTHREADS;
    constexpr int BC = (16 * (TBN / 4)) / NTHREADS;

    extern __shared__ uint32_t smem[];
    uint32_t* sAh = smem;
    uint32_t* sAl = smem + STAGES * ASZ;
    uint32_t* sBh = smem + 2 * STAGES * ASZ;
    uint32_t* sBl = smem + 2 * STAGES * ASZ + STAGES * BSZ;

    int z = blockIdx.z;
    int zo = z / Hsub, zi = z % Hsub;
    const uint32_t* Ahb = AH + zo * sAo + zi * sAi;
    const uint32_t* Alb = AL + zo * sAo + zi * sAi;
    const uint32_t* Bhb = BH + zo * sBo + zi * sBi;
    const uint32_t* Blb = BL + zo * sBo + zi * sBi;
    float*    Cb  = (PACKMODE == 0) ? (C + zo * sCo + zi * sCi) : nullptr;
    uint32_t* CHb = (PACKMODE != 0) ? (CH + zo * sCo + zi * sCi) : nullptr;
    uint32_t* CLb = (PACKMODE != 0) ? (CL + zo * sCo + zi * sCi) : nullptr;

    int tid = threadIdx.x;
    int wid = tid >> 5, lane = tid & 31;
    int wm = wid % WARPS_M, wn = wid / WARPS_M;
    int group = lane >> 2, tig = lane & 3;
    int row0 = blockIdx.x * TBM;
    int col0 = blockIdx.y * TBN;

    auto cpStage = [&](int k0, int st) {
        int kp0 = k0 >> 1;
        uint32_t ah0 = (uint32_t)__cvta_generic_to_shared(sAh + st * ASZ);
        uint32_t al0 = (uint32_t)__cvta_generic_to_shared(sAl + st * ASZ);
#pragma unroll
        for (int j = 0; j < AC; j++) {
            int ci = tid + j * NTHREADS;
            int rr = ci / (TBM / 4), cc = ci % (TBM / 4);
            long long go = (long long)(kp0 + rr) * ldap + row0 + cc * 4;
            uint32_t so = (rr * AS + cc * 4) * 4;
            cp_async16(ah0 + so, Ahb + go);
            cp_async16(al0 + so, Alb + go);
        }
        uint32_t bh0 = (uint32_t)__cvta_generic_to_shared(sBh + st * BSZ);
        uint32_t bl0 = (uint32_t)__cvta_generic_to_shared(sBl + st * BSZ);
#pragma unroll
        for (int j = 0; j < BC; j++) {
            int ci = tid + j * NTHREADS;
            int rr = ci / (TBN / 4), cc = ci % (TBN / 4);
            long long go = (long long)(kp0 + rr) * ldbp + col0 + cc * 4;
            uint32_t so = (rr * BS + cc * 4) * 4;
            cp_async16(bh0 + so, Bhb + go);
            cp_async16(bl0 + so, Blb + go);
        }
        CP_COMMIT();
    };

    float acc[MT][NT][4];
#pragma unroll
    for (int i = 0; i < MT; i++)
#pragma unroll
        for (int j = 0; j < NT; j++)
#pragma unroll
            for (int t = 0; t < 4; t++) acc[i][j][t] = 0.f;

    int kpref = 0;
#pragma unroll
    for (int s = 0; s < STAGES - 1; s++) { cpStage(kpref, s); kpref += 32; }

    int st = 0;
    for (int k0 = 0; k0 < K; k0 += 32) {
        if (kpref < K) {
            cpStage(kpref, (kpref >> 5) % STAGES);
            kpref += 32;
        }
        cp_wait_n(((kpref - k0) >> 5) - 1);
        __syncthreads();

        const uint32_t* Ahs = sAh + st * ASZ;
        const uint32_t* Als = sAl + st * ASZ;
        const uint32_t* Bhs = sBh + st * BSZ;
        const uint32_t* Bls = sBl + st * BSZ;
#pragma unroll
        for (int ks = 0; ks < 2; ks++) {
            uint32_t ah[MT][4], al[MT][4], bh[NT][2], bl[NT][2];
            int kp0 = ks * 8 + tig, kp1 = kp0 + 4;
#pragma unroll
            for (int mt = 0; mt < MT; mt++) {
                int r = wm * WM + mt * 16 + group;
                ah[mt][0] = Ahs[kp0 * AS + r];     al[mt][0] = Als[kp0 * AS + r];
                ah[mt][1] = Ahs[kp0 * AS + r + 8]; al[mt][1] = Als[kp0 * AS + r + 8];
                ah[mt][2] = Ahs[kp1 * AS + r];     al[mt][2] = Als[kp1 * AS + r];
                ah[mt][3] = Ahs[kp1 * AS + r + 8]; al[mt][3] = Als[kp1 * AS + r + 8];
            }
#pragma unroll
            for (int nt = 0; nt < NT; nt++) {
                int c = wn * WN + nt * 8 + group;
                bh[nt][0] = Bhs[kp0 * BS + c];  bl[nt][0] = Bls[kp0 * BS + c];
                bh[nt][1] = Bhs[kp1 * BS + c];  bl[nt][1] = Bls[kp1 * BS + c];
            }
#pragma unroll
            for (int mt = 0; mt < MT; mt++)
#pragma unroll
                for (int nt = 0; nt < NT; nt++)
                    mma16816(acc[mt][nt], ah[mt], bh[nt]);
#pragma unroll
            for (int mt = 0; mt < MT; mt++)
#pragma unroll
                for (int nt = 0; nt < NT; nt++)
                    mma16816(acc[mt][nt], al[mt], bh[nt]);
#pragma unroll
            for (int mt = 0; mt < MT; mt++)
#pragma unroll
                for (int nt = 0; nt < NT; nt++)
                    mma16816(acc[mt][nt], ah[mt], bl[nt]);
        }
        __syncthreads();
        if (++st == STAGES) st = 0;
    }

    int effMode = (PACKMODE == 3) ? ((zi >= rThresh) ? 2 : 1) : PACKMODE;

#pragma unroll
    for (int mt = 0; mt < MT; mt++) {
        int r = row0 + wm * WM + mt * 16 + group;
#pragma unroll
        for (int nt = 0; nt < NT; nt++) {
            int c = col0 + wn * WN + nt * 8 + tig * 2;
            float v00 = acc[mt][nt][0] * alpha;
            float v01 = acc[mt][nt][1] * alpha;
            float v10 = acc[mt][nt][2] * alpha;
            float v11 = acc[mt][nt][3] * alpha;
            if (doBias) {
                float2 bb = *reinterpret_cast<const float2*>(&bias[c]);
                v00 += bb.x; v01 += bb.y; v10 += bb.x; v11 += bb.y;
            }
            if (doRelu) {
                v00 = fmaxf(v00, 0.f); v01 = fmaxf(v01, 0.f);
                v10 = fmaxf(v10, 0.f); v11 = fmaxf(v11, 0.f);
            }
            if (PACKMODE == 0) {
                *reinterpret_cast<float2*>(&Cb[(long long)r * ldc + c])       = make_float2(v00, v01);
                *reinterpret_cast<float2*>(&Cb[(long long)(r + 8) * ldc + c]) = make_float2(v10, v11);
            } else if (effMode == 1) {
                long long base = (long long)(c >> 1) * ldc + r;
                uint32_t h, l;
                cvt_pair(v00, v01, h, l); CHb[base] = h;     CLb[base] = l;
                cvt_pair(v10, v11, h, l); CHb[base + 8] = h; CLb[base + 8] = l;
            } else {
                float u00 = __shfl_down_sync(0xffffffffu, v00, 4);
                float u01 = __shfl_down_sync(0xffffffffu, v01, 4);
                float u10 = __shfl_down_sync(0xffffffffu, v10, 4);
                float u11 = __shfl_down_sync(0xffffffffu, v11, 4);
                if (!(group & 1)) {
                    long long b0 = (long long)(r >> 1) * ldc2 + c;
                    long long b8 = (long long)((r + 8) >> 1) * ldc2 + c;
                    uint32_t h, l;
                    cvt_pair(v00, u00, h, l); CHb[b0]     = h; CLb[b0]     = l;
                    cvt_pair(v01, u01, h, l); CHb[b0 + 1] = h; CLb[b0 + 1] = l;
                    cvt_pair(v10, u10, h, l); CHb[b8]     = h; CLb[b8]     = l;
                    cvt_pair(v11, u11, h, l); CHb[b8 + 1] = h; CLb[b8 + 1] = l;
                }
            }
        }
    }
}

// ---------------- fused flash attention ----------------
#define FA_STRIDE 68
#define FA_TSZ (32 * FA_STRIDE)
__global__ __launch_bounds__(128)
void flash_attn(const uint32_t* __restrict__ Qh, const uint32_t* __restrict__ Ql,
                const uint32_t* __restrict__ Kh, const uint32_t* __restrict__ Kl,
                const uint32_t* __restrict__ Vh, const uint32_t* __restrict__ Vl,
                uint32_t* __restrict__ Oh, uint32_t* __restrict__ Ol, int causal)
{
    extern __shared__ uint32_t smem[];
    uint32_t* sKh = smem;
    uint32_t* sKl = smem + 2 * FA_TSZ;
    uint32_t* sVh = smem + 4 * FA_TSZ;
    uint32_t* sVl = smem + 6 * FA_TSZ;

    int qb = blockIdx.x;
    int b  = blockIdx.y / Hh;
    int h  = blockIdx.y % Hh;
    int tid = threadIdx.x;
    int wid = tid >> 5, lane = tid & 31;
    int group = lane >> 2, tig = lane & 3;
    int tokBase = b * Ss + qb * 64 + wid * 16;

    uint32_t qh[4][4], ql[4][4];
    const uint32_t SC = 0x3E003E00u;
#pragma unroll
    for (int ks = 0; ks < 4; ks++) {
        int kpa = h * 32 + ks * 8 + tig;
        long long b0 = (long long)kpa * TOK + tokBase + group;
        long long b2 = (long long)(kpa + 4) * TOK + tokBase + group;
        qh[ks][0] = mulbf2(Qh[b0], SC);     ql[ks][0] = mulbf2(Ql[b0], SC);
        qh[ks][1] = mulbf2(Qh[b0 + 8], SC); ql[ks][1] = mulbf2(Ql[b0 + 8], SC);
        qh[ks][2] = mulbf2(Qh[b2], SC);     ql[ks][2] = mulbf2(Ql[b2], SC);
        qh[ks][3] = mulbf2(Qh[b2 + 8], SC); ql[ks][3] = mulbf2(Ql[b2 + 8], SC);
    }

    float m0 = -INFINITY, m1 = -INFINITY, l0 = 0.f, l1 = 0.f;
    float acc_o[8][4];
#pragma unroll
    for (int nt = 0; nt < 8; nt++)
#pragma unroll
        for (int t = 0; t < 4; t++) acc_o[nt][t] = 0.f;

    int nkb = causal ? (qb + 1) : (Ss / 64);

    auto cpStage = [&](int kb, int stg) {
        uint32_t kh0 = (uint32_t)__cvta_generic_to_shared(sKh + stg * FA_TSZ);
        uint32_t kl0 = (uint32_t)__cvta_generic_to_shared(sKl + stg * FA_TSZ);
        uint32_t vh0 = (uint32_t)__cvta_generic_to_shared(sVh + stg * FA_TSZ);
        uint32_t vl0 = (uint32_t)__cvta_generic_to_shared(sVl + stg * FA_TSZ);
#pragma unroll
        for (int i = 0; i < 4; i++) {
            int idx = tid + i * 128;
            int row = idx >> 4, c4 = idx & 15;
            uint32_t so = (row * FA_STRIDE + c4 * 4) * 4;
            long long gK = (long long)(h * 32 + row) * TOK + b * Ss + kb * 64 + c4 * 4;
            cp_async16(kh0 + so, Kh + gK);
            cp_async16(kl0 + so, Kl + gK);
            long long gV = (long long)(b * (Ss / 2) + kb * 32 + row) * Dd + h * 64 + c4 * 4;
            cp_async16(vh0 + so, Vh + gV);
            cp_async16(vl0 + so, Vl + gV);
        }
        CP_COMMIT();
    };

    cpStage(0, 0);
    for (int kb = 0; kb < nkb; kb++) {
        if (kb + 1 < nkb) {
            cpStage(kb + 1, (kb + 1) & 1);
            asm volatile("cp.async.wait_group 1;");
        } else {
            asm volatile("cp.async.wait_group 0;");
        }
        __syncthreads();
        int stg = kb & 1;
        const uint32_t* Ksh = sKh + stg * FA_TSZ;
        const uint32_t* Ksl = sKl + stg * FA_TSZ;
        const uint32_t* Vsh = sVh + stg * FA_TSZ;
        const uint32_t* Vsl = sVl + stg * FA_TSZ;

        float s[8][4];
#pragma unroll
        for (int nt = 0; nt < 8; nt++)
#pragma unroll
            for (int t = 0; t < 4; t++) s[nt][t] = 0.f;
#pragma unroll
        for (int ks = 0; ks < 4; ks++) {
            int r0 = (ks * 8 + tig) * FA_STRIDE, r1 = r0 + 4 * FA_STRIDE;
            uint32_t bhf[8][2], blf[8][2];
#pragma unroll
            for (int nt = 0; nt < 8; nt++) {
                int c = nt * 8 + group;
                bhf[nt][0] = Ksh[r0 + c]; bhf[nt][1] = Ksh[r1 + c];
                blf[nt][0] = Ksl[r0 + c]; blf[nt][1] = Ksl[r1 + c];
            }
#pragma unroll
            for (int nt = 0; nt < 8; nt++) mma16816(s[nt], qh[ks], bhf[nt]);
#pragma unroll
            for (int nt = 0; nt < 8; nt++) mma16816(s[nt], ql[ks], bhf[nt]);
#pragma unroll
            for (int nt = 0; nt < 8; nt++) mma16816(s[nt], qh[ks], blf[nt]);
        }

        if (causal && kb == qb) {
            int r0 = wid * 16 + group, r1 = r0 + 8;
#pragma unroll
            for (int nt = 0; nt < 8; nt++) {
                int c0 = nt * 8 + tig * 2;
                if (c0     > r0) s[nt][0] = -1e9f;
                if (c0 + 1 > r0) s[nt][1] = -1e9f;
                if (c0     > r1) s[nt][2] = -1e9f;
                if (c0 + 1 > r1) s[nt][3] = -1e9f;
            }
        }

        float bm0 = -INFINITY, bm1 = -INFINITY;
#pragma unroll
        for (int nt = 0; nt < 8; nt++) {
            bm0 = fmaxf(bm0, fmaxf(s[nt][0], s[nt][1]));
            bm1 = fmaxf(bm1, fmaxf(s[nt][2], s[nt][3]));
        }
        bm0 = fmaxf(bm0, __shfl_xor_sync(0xffffffffu, bm0, 1));
        bm0 = fmaxf(bm0, __shfl_xor_sync(0xffffffffu, bm0, 2));
        bm1 = fmaxf(bm1, __shfl_xor_sync(0xffffffffu, bm1, 1));
        bm1 = fmaxf(bm1, __shfl_xor_sync(0xffffffffu, bm1, 2));
        float nm0 = fmaxf(m0, bm0), nm1 = fmaxf(m1, bm1);
        float a0f = __expf(m0 - nm0), a1f = __expf(m1 - nm1);
        m0 = nm0; m1 = nm1;
        float rs0 = 0.f, rs1 = 0.f;
#pragma unroll
        for (int nt = 0; nt < 8; nt++) {
            s[nt][0] = __expf(s[nt][0] - nm0);
            s[nt][1] = __expf(s[nt][1] - nm0);
            s[nt][2] = __expf(s[nt][2] - nm1);
            s[nt][3] = __expf(s[nt][3] - nm1);
            rs0 += s[nt][0] + s[nt][1];
            rs1 += s[nt][2] + s[nt][3];
        }
        rs0 += __shfl_xor_sync(0xffffffffu, rs0, 1);
        rs0 += __shfl_xor_sync(0xffffffffu, rs0, 2);
        rs1 += __shfl_xor_sync(0xffffffffu, rs1, 1);
        rs1 += __shfl_xor_sync(0xffffffffu, rs1, 2);
        l0 = l0 * a0f + rs0;
        l1 = l1 * a1f + rs1;
#pragma unroll
        for (int nt = 0; nt < 8; nt++) {
            acc_o[nt][0] *= a0f; acc_o[nt][1] *= a0f;
            acc_o[nt][2] *= a1f; acc_o[nt][3] *= a1f;
        }

        uint32_t ph[4][4], pl[4][4];
#pragma unroll
        for (int j = 0; j < 4; j++) {
            cvt_pair(s[2*j  ][0], s[2*j  ][1], ph[j][0], pl[j][0]);
            cvt_pair(s[2*j  ][2], s[2*j  ][3], ph[j][1], pl[j][1]);
            cvt_pair(s[2*j+1][0], s[2*j+1][1], ph[j][2], pl[j][2]);
            cvt_pair(s[2*j+1][2], s[2*j+1][3], ph[j][3], pl[j][3]);
        }

#pragma unroll
        for (int j = 0; j < 4; j++) {
            int r0 = (j * 8 + tig) * FA_STRIDE, r1 = r0 + 4 * FA_STRIDE;
            uint32_t vbh[8][2], vbl[8][2];
#pragma unroll
            for (int nt = 0; nt < 8; nt++) {
                int c = nt * 8 + group;
                vbh[nt][0] = Vsh[r0 + c]; vbh[nt][1] = Vsh[r1 + c];
                vbl[nt][0] = Vsl[r0 + c]; vbl[nt][1] = Vsl[r1 + c];
            }
#pragma unroll
            for (int nt = 0; nt < 8; nt++) mma16816(acc_o[nt], ph[j], vbh[nt]);
#pragma unroll
            for (int nt = 0; nt < 8; nt++) mma16816(acc_o[nt], pl[j], vbh[nt]);
#pragma unroll
            for (int nt = 0; nt < 8; nt++) mma16816(acc_o[nt], ph[j], vbl[nt]);
        }
        __syncthreads();
    }

    float inv0 = 1.0f / l0, inv1 = 1.0f / l1;
#pragma unroll
    for (int nt = 0; nt < 8; nt++) {
        int cp = h * 32 + nt * 4 + tig;
        long long bo = (long long)cp * TOK + tokBase + group;
        uint32_t hh, ll;
        cvt_pair(acc_o[nt][0] * inv0, acc_o[nt][1] * inv0, hh, ll);
        Oh[bo] = hh; Ol[bo] = ll;
        cvt_pair(acc_o[nt][2] * inv1, acc_o[nt][3] * inv1, hh, ll);
        Oh[bo + 8] = hh; Ol[bo + 8] = ll;
    }
}

// ---------------- vocab softmax ----------
__global__ __launch_bounds__(1024)
void softmax_vocab(float* __restrict__ P)
{
    float* p = P + (long long)blockIdx.x * Vv;
    int t = threadIdx.x;
    __shared__ float red[32];
    float v[32];
    float mx = -3.0e38f;
#pragma unroll
    for (int i = 0; i < 32; i++) {
        int idx = t + i * 1024;
        v[i] = (idx < Vv) ? p[idx] : -3.0e38f;
        mx = fmaxf(mx, v[i]);
    }
    for (int o = 16; o; o >>= 1) mx = fmaxf(mx, __shfl_xor_sync(0xffffffffu, mx, o));
    if ((t & 31) == 0) red[t >> 5] = mx;
    __syncthreads();
    if (t < 32) {
        float m2 = red[t];
        for (int o = 16; o; o >>= 1) m2 = fmaxf(m2, __shfl_xor_sync(0xffffffffu, m2, o));
        if (t == 0) red[0] = m2;
    }
    __syncthreads();
    mx = red[0];
    __syncthreads();
    float sum = 0.f;
#pragma unroll
    for (int i = 0; i < 32; i++) { v[i] = __expf(v[i] - mx); sum += v[i]; }
    for (int o = 16; o; o >>= 1) sum += __shfl_xor_sync(0xffffffffu, sum, o);
    if ((t & 31) == 0) red[t >> 5] = sum;
    __syncthreads();
    if (t < 32) {
        float s2 = red[t];
        for (int o = 16; o; o >>= 1) s2 += __shfl_xor_sync(0xffffffffu, s2, o);
        if (t == 0) red[0] = s2;
    }
    __syncthreads();
    float inv = 1.0f / red[0];
#pragma unroll
    for (int i = 0; i < 32; i++) {
        int idx = t + i * 1024;
        if (idx < Vv) p[idx] = v[i] * inv;
    }
}

// ---------------- fused add(x + s0 [+ s1] [+ bias]) + LN + coalesced pack ----------
__global__ __launch_bounds__(256)
void add_ln_pack8(float* __restrict__ x, const float* __restrict__ s0,
                  const float* __restrict__ s1, const float* __restrict__ bias,
                  uint32_t* __restrict__ H, uint32_t* __restrict__ L)
{
    __shared__ uint32_t sH[8][260];
    __shared__ uint32_t sL[8][260];
    int w = threadIdx.x >> 5, lane = threadIdx.x & 31;
    int row = blockIdx.x * 8 + w;
    float* xr = x + (long long)row * Dd;
    const float* sr0 = s0 + (long long)row * Dd;
    const float* sr1 = s1 ? (s1 + (long long)row * Dd) : nullptr;

    float2 v[8];
    float sum = 0.f;
#pragma unroll
    for (int j = 0; j < 8; j++) {
        int col = 2 * lane + 64 * j;
        float2 a = *reinterpret_cast<const float2*>(xr + col);
        float2 b = *reinterpret_cast<const float2*>(sr0 + col);
        v[j].x = a.x + b.x;
        v[j].y = a.y + b.y;
        if (sr1) {
            float2 c = *reinterpret_cast<const float2*>(sr1 + col);
            v[j].x += c.x; v[j].y += c.y;
        }
        if (bias) {
            float2 d = *reinterpret_cast<const float2*>(bias + col);
            v[j].x += d.x; v[j].y += d.y;
        }
        sum += v[j].x + v[j].y;
    }
    for (int o = 16; o; o >>= 1) sum += __shfl_xor_sync(0xffffffffu, sum, o);
    float mu = sum * (1.0f / 512.0f);
    float var = 0.f;
#pragma unroll
    for (int j = 0; j < 8; j++) {
        v[j].x -= mu; v[j].y -= mu;
        var += v[j].x * v[j].x + v[j].y * v[j].y;
    }
    for (int o = 16; o; o >>= 1) var += __shfl_xor_sync(0xffffffffu, var, o);
    float inv = rsqrtf(var * (1.0f / 512.0f) + 1e-5f);
#pragma unroll
    for (int j = 0; j < 8; j++) {
        v[j].x *= inv; v[j].y *= inv;
        *reinterpret_cast<float2*>(xr + 2 * lane + 64 * j) = v[j];
        uint32_t h, l; cvt_pair(v[j].x, v[j].y, h, l);
        sH[w][lane + 32 * j] = h;
        sL[w][lane + 32 * j] = l;
    }
    __syncthreads();
    int row0 = blockIdx.x * 8;
#pragma unroll
    for (int i = 0; i < 8; i++) {
        int idx = threadIdx.x + i * 256;
        int kp = idx >> 3, r = idx & 7;
        long long o = (long long)kp * TOK + row0 + r;
        H[o] = sH[r][kp];
        L[o] = sL[r][kp];
    }
}

// ---------------- embedding + PE + transposed pack ----------
__global__ __launch_bounds__(512)
void embed_pe_pack(const int* __restrict__ tok, const float* __restrict__ emb,
                   float* __restrict__ out,
                   uint32_t* __restrict__ H, uint32_t* __restrict__ L)
{
    int idx = blockIdx.x;
    int s = idx % Ss;
    int j = threadIdx.x;
    int tk = tok[idx];
    float ang = (float)s * powf(10000.0f, -2.0f * (float)j / 512.0f);
    float pe = (j & 1) ? cosf(ang) : sinf(ang);
    float v = emb[(long long)tk * Dd + j] + pe;
    out[(long long)idx * Dd + j] = v;

    float p = __shfl_down_sync(0xffffffffu, v, 1);
    if (!(j & 1)) {
        uint32_t h, l;
        cvt_pair(v, p, h, l);
        long long o = (long long)(j >> 1) * TOK + idx;
        H[o] = h; L[o] = l;
    }
}

// ---------------- host ----------------
static const int SM_AP64_3  = (4 * 3 * 16 * (64 + 8)) * 4;
static const int SM_AP128_3 = (4 * 3 * 16 * (128 + 8)) * 4;
static const int SM_FA      = 8 * FA_TSZ * 4;

struct GPtrs {
    float *x, *y, *tmp;
    uint32_t *encWh, *encWl, *decSWh, *decSWl, *decCWh, *decCWl;
    uint32_t *eW1h, *eW1l, *eW2h, *eW2l, *dW1h, *dW1l, *dW2h, *dW2l;
    uint32_t *oWh, *oWl;
    uint32_t *xTh, *xTl, *yTh, *yTl, *qkvPh, *qkvPl, *oTh, *oTl;
    uint32_t *xeTh, *xeTl, *xKVh, *xKVl, *fTh, *fTl;
};

// O-projection: split-K=2 into tmp slices [2][TOK*Dd]
static void oproj_splitk(GPtrs& G, const uint32_t* wh, const uint32_t* wl)
{
    dim3 g(TOK/64, Dd/64, 2);
    gemm_ap<64,64,128,2,3,0><<<g, 128, SM_AP64_3>>>(G.oTh, G.oTl, wh, wl,
        nullptr, G.tmp, nullptr, nullptr,
        256, TOK, Dd, Dd, Dd,
        0, 128LL * TOK, 0, 128LL * Dd, 0, TD, 2, 0, 1.0f, 0, 0);
}

static void run_mha_self(GPtrs& G, const uint32_t* aTh, const uint32_t* aTl,
                         const uint32_t* wh, const uint32_t* wl, bool causal)
{
    {
        dim3 g(TOK/64, Dd/64, 3);
        gemm_ap<64,64,128,2,3,3><<<g, 128, SM_AP64_3>>>(aTh, aTl, wh, wl,
            nullptr, nullptr, G.qkvPh, G.qkvPl,
            Dd, TOK, Dd, TOK, Dd,
            0, 0, 0, DD2, 0, KVC, 3, 2, 1.0f, 0, 0);
    }
    flash_attn<<<dim3(Ss/64, Bn*Hh), 128, SM_FA>>>(
        G.qkvPh, G.qkvPl, G.qkvPh + KVC, G.qkvPl + KVC,
        G.qkvPh + 2*KVC, G.qkvPl + 2*KVC, G.oTh, G.oTl, causal ? 1 : 0);
    oproj_splitk(G, wh + 3*DD2, wl + 3*DD2);
}

static void run_mha_cross(GPtrs& G, const uint32_t* aTh, const uint32_t* aTl, int layer,
                          const uint32_t* wh, const uint32_t* wl)
{
    {
        dim3 g(TOK/64, Dd/64, 1);
        gemm_ap<64,64,128,2,3,1><<<g, 128, SM_AP64_3>>>(aTh, aTl, wh, wl,
            nullptr, nullptr, G.qkvPh, G.qkvPl,
            Dd, TOK, Dd, TOK, Dd,
            0, 0, 0, 0, 0, 0, 1, 0, 1.0f, 0, 0);
    }
    const uint32_t* kh = G.xKVh + (long long)layer * 2 * KVC;
    const uint32_t* kl = G.xKVl + (long long)layer * 2 * KVC;
    flash_attn<<<dim3(Ss/64, Bn*Hh), 128, SM_FA>>>(
        G.qkvPh, G.qkvPl, kh, kl, kh + KVC, kl + KVC, G.oTh, G.oTl, 0);
    oproj_splitk(G, wh + 3*DD2, wl + 3*DD2);
}

static void run_ffn(GPtrs& G, const uint32_t* aTh, const uint32_t* aTl,
                    const uint32_t* w1h, const uint32_t* w1l, const float* b1,
                    const uint32_t* w2h, const uint32_t* w2l)
{
    {
        dim3 g(TOK/128, FFf/128, 1);
        gemm_ap<128,128,256,4,3,1><<<g, 256, SM_AP128_3>>>(aTh, aTl, w1h, w1l,
            b1, nullptr, G.fTh, G.fTl,
            Dd, TOK, FFf, TOK, Dd,
            0, 0, 0, 0, 0, 0, 1, 0, 1.0f, 1, 1);
    }
    {
        // FFN2 split-K=2 (bias deferred to the LN kernel)
        dim3 g(TOK/64, Dd/64, 2);
        gemm_ap<64,64,128,2,3,0><<<g, 128, SM_AP64_3>>>(G.fTh, G.fTl, w2h, w2l,
            nullptr, G.tmp, nullptr, nullptr,
            1024, TOK, Dd, Dd, Dd,
            0, 512LL * TOK, 0, 512LL * Dd, 0, TD, 2, 0, 1.0f, 0, 0);
    }
}

extern "C" void kernel_launch(void* const* d_in, const int* in_sizes, int n_in,
                              void* d_out, int out_size)
{
    const int*   src           = (const int*)  d_in[0];
    const int*   trg           = (const int*)  d_in[1];
    const float* src_emb       = (const float*)d_in[2];
    const float* trg_emb       = (const float*)d_in[3];
    const float* enc_qkvo      = (const float*)d_in[4];
    const float* enc_ffn_w1    = (const float*)d_in[5];
    const float* enc_ffn_b1    = (const float*)d_in[6];
    const float* enc_ffn_w2    = (const float*)d_in[7];
    const float* enc_ffn_b2    = (const float*)d_in[8];
    const float* dec_self_qkvo = (const float*)d_in[9];
    const float* dec_cross_qkvo= (const float*)d_in[10];
    const float* dec_ffn_w1    = (const float*)d_in[11];
    const float* dec_ffn_b1    = (const float*)d_in[12];
    const float* dec_ffn_w2    = (const float*)d_in[13];
    const float* dec_ffn_b2    = (const float*)d_in[14];
    const float* out_w         = (const float*)d_in[15];
    const float* out_b         = (const float*)d_in[16];
    float* out = (float*)d_out;

    cudaFuncSetAttribute(gemm_ap<64,64,128,2,3,0>,
                         cudaFuncAttributeMaxDynamicSharedMemorySize, SM_AP64_3);
    cudaFuncSetAttribute(gemm_ap<64,64,128,2,3,1>,
                         cudaFuncAttributeMaxDynamicSharedMemorySize, SM_AP64_3);
    cudaFuncSetAttribute(gemm_ap<64,64,128,2,3,3>,
                         cudaFuncAttributeMaxDynamicSharedMemorySize, SM_AP64_3);
    cudaFuncSetAttribute(gemm_ap<128,128,256,4,3,0>,
                         cudaFuncAttributeMaxDynamicSharedMemorySize, SM_AP128_3);
    cudaFuncSetAttribute(gemm_ap<128,128,256,4,3,1>,
                         cudaFuncAttributeMaxDynamicSharedMemorySize, SM_AP128_3);
    cudaFuncSetAttribute(flash_attn,
                         cudaFuncAttributeMaxDynamicSharedMemorySize, SM_FA);

    GPtrs G;
    cudaGetSymbolAddress((void**)&G.x,    g_x);
    cudaGetSymbolAddress((void**)&G.y,    g_y);
    cudaGetSymbolAddress((void**)&G.tmp,  g_tmp);
    cudaGetSymbolAddress((void**)&G.encWh,  g_encW_h);  cudaGetSymbolAddress((void**)&G.encWl, g_encW_l);
    cudaGetSymbolAddress((void**)&G.decSWh, g_decSW_h); cudaGetSymbolAddress((void**)&G.decSWl, g_decSW_l);
    cudaGetSymbolAddress((void**)&G.decCWh, g_decCW_h); cudaGetSymbolAddress((void**)&G.decCWl, g_decCW_l);
    cudaGetSymbolAddress((void**)&G.eW1h,   g_encW1_h); cudaGetSymbolAddress((void**)&G.eW1l, g_encW1_l);
    cudaGetSymbolAddress((void**)&G.eW2h,   g_encW2_h); cudaGetSymbolAddress((void**)&G.eW2l, g_encW2_l);
    cudaGetSymbolAddress((void**)&G.dW1h,   g_decW1_h); cudaGetSymbolAddress((void**)&G.dW1l, g_decW1_l);
    cudaGetSymbolAddress((void**)&G.dW2h,   g_decW2_h); cudaGetSymbolAddress((void**)&G.dW2l, g_decW2_l);
    cudaGetSymbolAddress((void**)&G.oWh,    g_outW_h);  cudaGetSymbolAddress((void**)&G.oWl, g_outW_l);
    cudaGetSymbolAddress((void**)&G.xTh,    g_xT_h);    cudaGetSymbolAddress((void**)&G.xTl, g_xT_l);
    cudaGetSymbolAddress((void**)&G.yTh,    g_yT_h);    cudaGetSymbolAddress((void**)&G.yTl, g_yT_l);
    cudaGetSymbolAddress((void**)&G.qkvPh,  g_qkvP_h);  cudaGetSymbolAddress((void**)&G.qkvPl, g_qkvP_l);
    cudaGetSymbolAddress((void**)&G.oTh,    g_oT_h);    cudaGetSymbolAddress((void**)&G.oTl, g_oT_l);
    cudaGetSymbolAddress((void**)&G.xeTh,   g_xeT_h);   cudaGetSymbolAddress((void**)&G.xeTl, g_xeT_l);
    cudaGetSymbolAddress((void**)&G.xKVh,   g_xKV_h);   cudaGetSymbolAddress((void**)&G.xKVl, g_xKV_l);
    cudaGetSymbolAddress((void**)&G.fTh,    g_fT_h);    cudaGetSymbolAddress((void**)&G.fTl, g_fT_l);

    // weight conversions (once per call)
    convB<<<dim3(Dd / 256,  24 * Dd / 2), 256>>>(enc_qkvo,       G.encWh, G.encWl, Dd);
    convB<<<dim3(Dd / 256,  24 * Dd / 2), 256>>>(dec_self_qkvo,  G.decSWh, G.decSWl, Dd);
    convB<<<dim3(Dd / 256,  24 * Dd / 2), 256>>>(dec_cross_qkvo, G.decCWh, G.decCWl, Dd);
    convB<<<dim3(FFf / 256, Nl * Dd / 2), 256>>>(enc_ffn_w1, G.eW1h, G.eW1l, FFf);
    convB<<<dim3(Dd / 256,  Nl * FFf / 2), 256>>>(enc_ffn_w2, G.eW2h, G.eW2l, Dd);
    convB<<<dim3(FFf / 256, Nl * Dd / 2), 256>>>(dec_ffn_w1, G.dW1h, G.dW1l, FFf);
    convB<<<dim3(Dd / 256,  Nl * FFf / 2), 256>>>(dec_ffn_w2, G.dW2h, G.dW2l, Dd);
    convB<<<dim3(Vv / 256,  Dd / 2), 256>>>(out_w, G.oWh, G.oWl, Vv);

    embed_pe_pack<<<TOK, 512>>>(src, src_emb, G.x, G.xTh, G.xTl);
    embed_pe_pack<<<TOK, 512>>>(trg, trg_emb, G.y, G.yTh, G.yTl);

    // ---------------- Encoder ----------------
    for (int i = 0; i < Nl; i++) {
        run_mha_self(G, G.xTh, G.xTl,
                G.encWh + (long long)i * 4 * DD2, G.encWl + (long long)i * 4 * DD2, false);
        add_ln_pack8<<<TOK/8, 256>>>(G.x, G.tmp, G.tmp + TD, nullptr, G.xTh, G.xTl);
        run_ffn(G, G.xTh, G.xTl,
                G.eW1h + (long long)i * W1SZ, G.eW1l + (long long)i * W1SZ,
                enc_ffn_b1 + (long long)i * FFf,
                G.eW2h + (long long)i * W1SZ, G.eW2l + (long long)i * W1SZ);
        if (i == Nl - 1)
            add_ln_pack8<<<TOK/8, 256>>>(G.x, G.tmp, G.tmp + TD,
                enc_ffn_b2 + (long long)i * Dd, G.xeTh, G.xeTl);
        else
            add_ln_pack8<<<TOK/8, 256>>>(G.x, G.tmp, G.tmp + TD,
                enc_ffn_b2 + (long long)i * Dd, G.xTh, G.xTl);
    }

    // precompute ALL cross-attn K,V (6 layers) from packed encoder output
    {
        dim3 g(TOK/64, Dd/64, 2 * Nl);
        gemm_ap<64,64,128,2,3,3><<<g, 128, SM_AP64_3>>>(G.xeTh, G.xeTl,
            G.decCWh + DD2, G.decCWl + DD2,
            nullptr, nullptr, G.xKVh, G.xKVl,
            Dd, TOK, Dd, TOK, Dd,
            0, 0, (long long)4 * DD2, DD2, (long long)2 * KVC, KVC,
            2, 1, 1.0f, 0, 0);
    }

    // ---------------- Decoder ----------------
    for (int i = 0; i < Nl; i++) {
        run_mha_self(G, G.yTh, G.yTl,
                G.decSWh + (long long)i * 4 * DD2, G.decSWl + (long long)i * 4 * DD2, true);
        add_ln_pack8<<<TOK/8, 256>>>(G.y, G.tmp, G.tmp + TD, nullptr, G.yTh, G.yTl);

        run_mha_cross(G, G.yTh, G.yTl, i,
                G.decCWh + (long long)i * 4 * DD2, G.decCWl + (long long)i * 4 * DD2);
        add_ln_pack8<<<TOK/8, 256>>>(G.y, G.tmp, G.tmp + TD, nullptr, G.yTh, G.yTl);

        run_ffn(G, G.yTh, G.yTl,
                G.dW1h + (long long)i * W1SZ, G.dW1l + (long long)i * W1SZ,
                dec_ffn_b1 + (long long)i * FFf,
                G.dW2h + (long long)i * W1SZ, G.dW2l + (long long)i * W1SZ);
        add_ln_pack8<<<TOK/8, 256>>>(G.y, G.tmp, G.tmp + TD,
            dec_ffn_b2 + (long long)i * Dd, G.yTh, G.yTl);
    }

    // ---------------- Output projection + vocab softmax ----------------
    {
        dim3 g(TOK/128, Vv/128, 1);
        gemm_ap<128,128,256,4,3,0><<<g, 256, SM_AP128_3>>>(G.yTh, G.yTl, G.oWh, G.oWl,
            out_b, out, nullptr, nullptr,
            Dd, TOK, Vv, Vv, Dd,
            0, 0, 0, 0, 0, 0, 1, 0, 1.0f, 1, 0);
    }
    softmax_vocab<<<TOK, 1024>>>(out);
}